// round 2
// baseline (speedup 1.0000x reference)
#include <cuda_runtime.h>
#include <cuda_bf16.h>

// Problem constants (fixed by setup_inputs)
#define NN 50000
#define EE 400000
#define HD 128
#define FIN 16
#define EAD 8
#define MAX_LAYERS 6
#define NODE_OUT_ELEMS (NN * 2)

// ---------------- scratch (device globals; no allocation allowed) ----------------
__device__ float g_h[NN * HD];
__device__ float g_h2[NN * HD];
__device__ float g_A[NN * HD];
__device__ float g_P[NN * HD];
__device__ float g_Q[NN * HD];
__device__ float g_U[HD * HD];
__device__ float g_V[HD * HD];
__device__ float g_c1[HD];

__device__ int g_src[EE];
__device__ int g_dst[EE];
__device__ int g_csrc[EE];     // CSR by dst: concatenated src ids
__device__ int g_deg[NN];
__device__ int g_rowptr[NN + 1];
__device__ int g_cursor[NN];
__device__ int g_zlist[NN];
__device__ int g_zcount;
__device__ int g_is64;

// ---------------- edge_index dtype detection ----------------
__global__ void detect_kernel(const long long* ei) {
    __shared__ int bad;
    if (threadIdx.x == 0) bad = 0;
    __syncthreads();
    for (int i = threadIdx.x; i < 1024; i += blockDim.x) {
        long long v = ei[i];
        if (v < 0 || v >= NN) bad = 1;
    }
    __syncthreads();
    if (threadIdx.x == 0) g_is64 = bad ? 0 : 1;
}

// ---------------- prep: convert + zero ----------------
__global__ void prep_kernel(const void* ei) {
    int idx = blockIdx.x * blockDim.x + threadIdx.x;
    int stride = gridDim.x * blockDim.x;
    int is64 = g_is64;
    const long long* p64 = (const long long*)ei;
    const int* p32 = (const int*)ei;
    for (int i = idx; i < EE; i += stride) {
        if (is64) {
            g_src[i] = (int)p64[i];
            g_dst[i] = (int)p64[EE + i];
        } else {
            g_src[i] = p32[i];
            g_dst[i] = p32[EE + i];
        }
        if (i < NN) g_deg[i] = 0;
    }
    if (idx == 0) g_zcount = 0;
}

__global__ void hist_kernel() {
    int idx = blockIdx.x * blockDim.x + threadIdx.x;
    int stride = gridDim.x * blockDim.x;
    for (int i = idx; i < EE; i += stride) atomicAdd(&g_deg[g_dst[i]], 1);
}

// single-block exclusive scan of g_deg -> g_rowptr
__global__ void scan_kernel() {
    __shared__ int sh[1024];
    __shared__ int runsh;
    int tid = threadIdx.x;
    if (tid == 0) runsh = 0;
    __syncthreads();
    for (int base = 0; base < NN; base += 1024) {
        int i = base + tid;
        int v = (i < NN) ? g_deg[i] : 0;
        sh[tid] = v;
        __syncthreads();
        for (int off = 1; off < 1024; off <<= 1) {
            int t = (tid >= off) ? sh[tid - off] : 0;
            __syncthreads();
            sh[tid] += t;
            __syncthreads();
        }
        int runl = runsh;
        if (i < NN) g_rowptr[i] = runl + sh[tid] - v;
        __syncthreads();
        if (tid == 0) runsh = runl + sh[1023];
        __syncthreads();
    }
    if (tid == 0) g_rowptr[NN] = runsh;
}

__global__ void nodeprep_kernel() {
    int idx = blockIdx.x * blockDim.x + threadIdx.x;
    int stride = gridDim.x * blockDim.x;
    for (int i = idx; i < NN; i += stride) {
        g_cursor[i] = g_rowptr[i];
        if (g_deg[i] == 0) {
            int p = atomicAdd(&g_zcount, 1);
            g_zlist[p] = i;
        }
    }
}

__global__ void scatter_kernel() {
    int idx = blockIdx.x * blockDim.x + threadIdx.x;
    int stride = gridDim.x * blockDim.x;
    for (int i = idx; i < EE; i += stride) {
        int d = g_dst[i];
        int pos = atomicAdd(&g_cursor[d], 1);
        g_csrc[pos] = g_src[i];
    }
}

// ---------------- combined layer weights: U = Wu_a + Wb@Wu_b, V = Wt@Wu_b ----------------
__global__ void uv_kernel(const float* __restrict__ Wmsg, const float* __restrict__ bmsg,
                          const float* __restrict__ Wupd, const float* __restrict__ bupd) {
    int k = blockIdx.x;   // 0..127
    int j = threadIdx.x;  // 0..127
    float u = Wupd[k * HD + j];
    float v = 0.f;
    for (int t = 0; t < HD; t++) {
        float wub = Wupd[(HD + t) * HD + j];
        u += Wmsg[(HD + k) * HD + t] * wub;   // Wb[k][t]
        v += Wmsg[k * HD + t] * wub;          // Wt[k][t]
    }
    g_U[k * HD + j] = u;
    g_V[k * HD + j] = v;
    if (k == 0) {
        float c = bupd[j];
        for (int t = 0; t < HD; t++) c += bmsg[t] * Wupd[(HD + t) * HD + j];
        g_c1[j] = c;
    }
}

// ---------------- encoder: h = x @ W_enc + b_enc ----------------
__global__ void encoder_kernel(const float* __restrict__ x, const float* __restrict__ Wenc,
                               const float* __restrict__ benc) {
    __shared__ float ws[FIN * HD];
    __shared__ float bs[HD];
    __shared__ float xs[FIN];
    int tid = threadIdx.x;  // 128
    for (int i = tid; i < FIN * HD; i += 128) ws[i] = Wenc[i];
    bs[tid] = benc[tid];
    __syncthreads();
    for (int v = blockIdx.x; v < NN; v += gridDim.x) {
        if (tid < FIN) xs[tid] = x[v * FIN + tid];
        __syncthreads();
        float acc = bs[tid];
#pragma unroll
        for (int k = 0; k < FIN; k++) acc += xs[k] * ws[k * HD + tid];
        g_h[v * HD + tid] = acc;
        __syncthreads();
    }
}

// ---------------- aggregation: A[v] = mean over in-edges of h[src] ----------------
__global__ void agg_kernel(const int* __restrict__ lnum, int layer) {
    if (layer >= *lnum) return;
    int j = threadIdx.x;  // 128
    for (int v = blockIdx.x; v < NN; v += gridDim.x) {
        int s0 = g_rowptr[v], s1 = g_rowptr[v + 1];
        float acc = 0.f;
        for (int idx = s0; idx < s1; idx++) acc += g_h[g_csrc[idx] * HD + j];
        int dg = s1 - s0;
        float dd = dg > 0 ? (float)dg : 1.f;
        g_A[v * HD + j] = acc / dd;
    }
}

// ---------------- generic C = act(X1@W1 [+ X2@W2] + bias), W [128,128], C [NN,128] ----------
__global__ void gemm_kernel(const float* __restrict__ X1, const float* __restrict__ W1,
                            const float* __restrict__ X2, const float* __restrict__ W2,
                            const float* __restrict__ bias, float* __restrict__ C,
                            int doRelu, const int* __restrict__ lnum, int layer) {
    if (layer >= 0 && layer >= *lnum) return;
    __shared__ float Xs[64 * 8];
    int tid = threadIdx.x;       // 256
    int tx = tid & 31, ty = tid >> 5;
    int row0 = blockIdx.x * 64;
    int c0 = tx * 4;
    float acc[8][4];
    if (bias) {
        float4 b = *(const float4*)(bias + c0);
#pragma unroll
        for (int i = 0; i < 8; i++) { acc[i][0] = b.x; acc[i][1] = b.y; acc[i][2] = b.z; acc[i][3] = b.w; }
    } else {
#pragma unroll
        for (int i = 0; i < 8; i++) { acc[i][0] = 0.f; acc[i][1] = 0.f; acc[i][2] = 0.f; acc[i][3] = 0.f; }
    }
    const float* X = X1;
    const float* W = W1;
    for (int pass = 0; pass < 2; pass++) {
        if (pass == 1) {
            if (!X2) break;
            X = X2; W = W2;
        }
        for (int k0 = 0; k0 < HD; k0 += 8) {
            {
                int e = tid, rl = e >> 3, kk = e & 7, r = row0 + rl;
                Xs[e] = (r < NN) ? X[r * HD + k0 + kk] : 0.f;
                e = tid + 256; rl = e >> 3; kk = e & 7; r = row0 + rl;
                Xs[e] = (r < NN) ? X[r * HD + k0 + kk] : 0.f;
            }
            __syncthreads();
#pragma unroll
            for (int kk = 0; kk < 8; kk++) {
                float4 w = *(const float4*)(W + (k0 + kk) * HD + c0);
#pragma unroll
                for (int i = 0; i < 8; i++) {
                    float xv = Xs[(i * 8 + ty) * 8 + kk];
                    acc[i][0] += xv * w.x; acc[i][1] += xv * w.y;
                    acc[i][2] += xv * w.z; acc[i][3] += xv * w.w;
                }
            }
            __syncthreads();
        }
    }
#pragma unroll
    for (int i = 0; i < 8; i++) {
        int r = row0 + i * 8 + ty;
        if (r < NN) {
            float4 o;
            o.x = acc[i][0]; o.y = acc[i][1]; o.z = acc[i][2]; o.w = acc[i][3];
            if (doRelu) {
                o.x = fmaxf(o.x, 0.f); o.y = fmaxf(o.y, 0.f);
                o.z = fmaxf(o.z, 0.f); o.w = fmaxf(o.w, 0.f);
            }
            *(float4*)(C + r * HD + c0) = o;
        }
    }
}

// ---------------- fixup for zero-in-degree nodes: h2 = relu(h@Wu_a + b_upd) ----------------
__global__ void fixup_kernel(const float* __restrict__ Wupd, const float* __restrict__ bupd,
                             const int* __restrict__ lnum, int layer) {
    if (layer >= *lnum) return;
    __shared__ float hs[HD];
    int tid = threadIdx.x;  // 128
    int zc = g_zcount;
    for (int zi = blockIdx.x; zi < zc; zi += gridDim.x) {
        int v = g_zlist[zi];
        hs[tid] = g_h[v * HD + tid];
        __syncthreads();
        float acc = bupd[tid];
#pragma unroll 8
        for (int k = 0; k < HD; k++) acc += hs[k] * Wupd[k * HD + tid];
        g_h2[v * HD + tid] = fmaxf(acc, 0.f);
        __syncthreads();
    }
}

__global__ void copy_kernel(const int* __restrict__ lnum, int layer) {
    if (layer >= *lnum) return;
    int idx = blockIdx.x * blockDim.x + threadIdx.x;
    int stride = gridDim.x * blockDim.x;
    const float4* s = (const float4*)g_h2;
    float4* d = (float4*)g_h;
    for (int i = idx; i < NN * HD / 4; i += stride) d[i] = s[i];
}

// ---------------- node head: out = relu(h@Wn1+bn1)@Wn2+bn2 ----------------
__global__ void nodehead_kernel(const float* __restrict__ Wn1, const float* __restrict__ bn1,
                                const float* __restrict__ Wn2, const float* __restrict__ bn2,
                                float* __restrict__ out) {
    __shared__ float w1s[HD * 64];
    __shared__ float w2s[64 * 2];
    __shared__ float hs[HD];
    __shared__ float ts[64];
    int tid = threadIdx.x;  // 64
    for (int i = tid; i < HD * 64; i += 64) w1s[i] = Wn1[i];
    for (int i = tid; i < 128; i += 64) w2s[i] = Wn2[i];
    __syncthreads();
    for (int v = blockIdx.x; v < NN; v += gridDim.x) {
        hs[tid] = g_h[v * HD + tid];
        hs[tid + 64] = g_h[v * HD + tid + 64];
        __syncthreads();
        float acc = bn1[tid];
#pragma unroll 8
        for (int k = 0; k < HD; k++) acc += hs[k] * w1s[k * 64 + tid];
        ts[tid] = fmaxf(acc, 0.f);
        __syncthreads();
        if (tid < 2) {
            float a0 = 0.f, a1 = 0.f, a2 = 0.f, a3 = 0.f;
#pragma unroll
            for (int j = 0; j < 64; j += 4) {
                a0 += ts[j] * w2s[j * 2 + tid];
                a1 += ts[j + 1] * w2s[(j + 1) * 2 + tid];
                a2 += ts[j + 2] * w2s[(j + 2) * 2 + tid];
                a3 += ts[j + 3] * w2s[(j + 3) * 2 + tid];
            }
            out[v * 2 + tid] = bn2[tid] + a0 + a1 + a2 + a3;
        }
        __syncthreads();
    }
}

// ---------------- fused edge head ----------------
// t = relu(P[src] + Q[dst] + ea@We1c + be1); u = relu(t@We2 + be2); out = u@We3 + be3
// Per iteration: 64 edges. Phase2 register-tiled 4 edges x 4 cols per thread.
#define SMEM_EDGE_FLOATS (1024 + 8192 + 384 + 128 + 64 + 8 + 128 * 68 + 64 * 64 + 512 + 64)
__global__ void edge_kernel(const float* __restrict__ ea, const float* __restrict__ We1,
                            const float* __restrict__ be1, const float* __restrict__ We2,
                            const float* __restrict__ be2, const float* __restrict__ We3,
                            const float* __restrict__ be3, float* __restrict__ out) {
    extern __shared__ float sm[];
    float* wc = sm;              // 8x128 = 1024
    float* w2 = wc + 1024;       // 128x64 = 8192
    float* w3 = w2 + 8192;       // 64x6 = 384
    float* b1 = w3 + 384;        // 128
    float* b2 = b1 + 128;        // 64
    float* b3 = b2 + 64;         // 8 (padded)
    float* ts = b3 + 8;          // 128 x 68 (padded stride) = 8704
    float* us = ts + 128 * 68;   // 64 x 64 = 4096
    float* eas = us + 4096;      // 64 x 8 = 512
    int* ss = (int*)(eas + 512); // 64 src + 64 dst (as ints)
    int* ds = ss + 32;           // note: ss,ds interleaved in 64-float region? keep separate:
    // (use the 64-float block: first 32 floats as 32 ints is wrong; redo below with proper sizes)
    // We sized SMEM_EDGE_FLOATS with a final 64-float block: 64 ints src + (reuse) — instead:
    // put src in first 64 ints and dst in... we need 128 ints = 512B = 128 floats.
    // SMEM_EDGE_FLOATS includes 64 extra floats; we also steal the b3 padding region carefully.
    // Simpler: src/dst live in the 'eas+512' region of 64 floats + reuse top of ts padding.
    (void)ds;
    int* ssrc = (int*)(eas + 512);        // 64 ints (256 B)  -> uses the trailing 64-float block
    // dst: reuse padding columns of ts (cols 64..67 of rows 0..15 == 64 slots), safe:
    // ts row k has stride 68, data in [0,64); pad [64,68). Use rows 0..15 pad -> 64 ints.
    int tid = threadIdx.x;  // 256

    for (int i = tid; i < 1024; i += 256) wc[i] = We1[256 * HD + i];
    for (int i = tid; i < 8192; i += 256) w2[i] = We2[i];
    for (int i = tid; i < 384; i += 256) w3[i] = We3[i];
    if (tid < 128) b1[tid] = be1[tid];
    if (tid < 64) b2[tid] = be2[tid];
    if (tid < 6) b3[tid] = be3[tid];
    __syncthreads();

    int eb = (tid & 15) * 4;
    int jb = (tid >> 4) * 4;

    for (int e0 = blockIdx.x * 64; e0 < EE; e0 += gridDim.x * 64) {
        if (tid < 64) {
            int e = e0 + tid;
            ssrc[tid] = (e < EE) ? g_src[e] : 0;
            int d = (e < EE) ? g_dst[e] : 0;
            ((int*)ts)[(tid >> 2) * 68 + 64 + (tid & 3)] = d;  // pad slots rows 0..15
        }
        for (int idx = tid; idx < 512; idx += 256) {
            int el = idx >> 3;
            int e = e0 + el;
            eas[idx] = (e < EE) ? ea[e * EAD + (idx & 7)] : 0.f;
        }
        __syncthreads();
        // phase 1: t[j][el]
        for (int r = 0; r < 32; r++) {
            int idx = tid + 256 * r;
            int el = idx >> 7, j = idx & 127;
            int e = e0 + el;
            float acc = b1[j];
#pragma unroll
            for (int k = 0; k < EAD; k++) acc += eas[el * 8 + k] * wc[k * HD + j];
            if (e < EE) {
                int s = ssrc[el];
                int d = ((int*)ts)[(el >> 2) * 68 + 64 + (el & 3)];
                acc += g_P[s * HD + j] + g_Q[d * HD + j];
            }
            ts[j * 68 + el] = fmaxf(acc, 0.f);
        }
        __syncthreads();
        // phase 2: u = relu(t@We2 + be2), thread tile 4 edges x 4 cols
        float acc2[4][4];
#pragma unroll
        for (int ji = 0; ji < 4; ji++) {
            float b = b2[jb + ji];
            acc2[0][ji] = b; acc2[1][ji] = b; acc2[2][ji] = b; acc2[3][ji] = b;
        }
#pragma unroll 8
        for (int k = 0; k < HD; k++) {
            float4 tv = *(const float4*)(ts + k * 68 + eb);
            float4 wv = *(const float4*)(w2 + k * 64 + jb);
            acc2[0][0] += tv.x * wv.x; acc2[0][1] += tv.x * wv.y; acc2[0][2] += tv.x * wv.z; acc2[0][3] += tv.x * wv.w;
            acc2[1][0] += tv.y * wv.x; acc2[1][1] += tv.y * wv.y; acc2[1][2] += tv.y * wv.z; acc2[1][3] += tv.y * wv.w;
            acc2[2][0] += tv.z * wv.x; acc2[2][1] += tv.z * wv.y; acc2[2][2] += tv.z * wv.z; acc2[2][3] += tv.z * wv.w;
            acc2[3][0] += tv.w * wv.x; acc2[3][1] += tv.w * wv.y; acc2[3][2] += tv.w * wv.z; acc2[3][3] += tv.w * wv.w;
        }
#pragma unroll
        for (int ei = 0; ei < 4; ei++) {
            float4 o;
            o.x = fmaxf(acc2[ei][0], 0.f); o.y = fmaxf(acc2[ei][1], 0.f);
            o.z = fmaxf(acc2[ei][2], 0.f); o.w = fmaxf(acc2[ei][3], 0.f);
            *(float4*)(us + (eb + ei) * 64 + jb) = o;
        }
        __syncthreads();
        // phase 3: out = u@We3 + be3
        for (int oi = tid; oi < 384; oi += 256) {
            int el = oi / 6, o = oi % 6;
            float a0 = 0.f, a1 = 0.f, a2 = 0.f, a3 = 0.f;
#pragma unroll
            for (int j = 0; j < 64; j += 4) {
                a0 += us[el * 64 + j] * w3[j * 6 + o];
                a1 += us[el * 64 + j + 1] * w3[(j + 1) * 6 + o];
                a2 += us[el * 64 + j + 2] * w3[(j + 2) * 6 + o];
                a3 += us[el * 64 + j + 3] * w3[(j + 3) * 6 + o];
            }
            int e = e0 + el;
            if (e < EE) out[e * 6 + o] = b3[o] + a0 + a1 + a2 + a3;
        }
        __syncthreads();
    }
}

// ---------------- launch ----------------
extern "C" void kernel_launch(void* const* d_in, const int* in_sizes, int n_in,
                              void* d_out, int out_size) {
    const float* x    = (const float*)d_in[0];
    const void*  ei   = d_in[1];
    const float* ea   = (const float*)d_in[2];
    const int*   lnum = (const int*)d_in[3];
    const float* Wenc = (const float*)d_in[4];
    const float* benc = (const float*)d_in[5];
    const float* Wmsg = (const float*)d_in[6];
    const float* bmsg = (const float*)d_in[7];
    const float* Wupd = (const float*)d_in[8];
    const float* bupd = (const float*)d_in[9];
    const float* Wn1  = (const float*)d_in[10];
    const float* bn1  = (const float*)d_in[11];
    const float* Wn2  = (const float*)d_in[12];
    const float* bn2  = (const float*)d_in[13];
    const float* We1  = (const float*)d_in[14];
    const float* be1  = (const float*)d_in[15];
    const float* We2  = (const float*)d_in[16];
    const float* be2  = (const float*)d_in[17];
    const float* We3  = (const float*)d_in[18];
    const float* be3  = (const float*)d_in[19];
    float* out = (float*)d_out;

    float *hp, *h2p, *Ap, *Pp, *Qp, *Up, *Vp, *c1p;
    cudaGetSymbolAddress((void**)&hp,  g_h);
    cudaGetSymbolAddress((void**)&h2p, g_h2);
    cudaGetSymbolAddress((void**)&Ap,  g_A);
    cudaGetSymbolAddress((void**)&Pp,  g_P);
    cudaGetSymbolAddress((void**)&Qp,  g_Q);
    cudaGetSymbolAddress((void**)&Up,  g_U);
    cudaGetSymbolAddress((void**)&Vp,  g_V);
    cudaGetSymbolAddress((void**)&c1p, g_c1);

    const int smemEdge = SMEM_EDGE_FLOATS * 4;
    cudaFuncSetAttribute(edge_kernel, cudaFuncAttributeMaxDynamicSharedMemorySize, smemEdge);

    detect_kernel<<<1, 256>>>((const long long*)ei);
    prep_kernel<<<2048, 256>>>(ei);
    hist_kernel<<<2048, 256>>>();
    scan_kernel<<<1, 1024>>>();
    nodeprep_kernel<<<512, 256>>>();
    scatter_kernel<<<2048, 256>>>();
    uv_kernel<<<128, 128>>>(Wmsg, bmsg, Wupd, bupd);
    encoder_kernel<<<1184, 128>>>(x, Wenc, benc);

    const int gemmGrid = (NN + 63) / 64;  // 782
    for (int L = 0; L < MAX_LAYERS; L++) {
        agg_kernel<<<2048, 128>>>(lnum, L);
        gemm_kernel<<<gemmGrid, 256>>>(hp, Up, Ap, Vp, c1p, h2p, 1, lnum, L);
        fixup_kernel<<<64, 128>>>(Wupd, bupd, lnum, L);
        copy_kernel<<<2048, 256>>>(lnum, L);
    }

    nodehead_kernel<<<2048, 64>>>(Wn1, bn1, Wn2, bn2, out);
    // P = h @ We1[0:128], Q = h @ We1[128:256]
    gemm_kernel<<<gemmGrid, 256>>>(hp, We1, nullptr, nullptr, nullptr, Pp, 0, lnum, -1);
    gemm_kernel<<<gemmGrid, 256>>>(hp, We1 + 128 * HD, nullptr, nullptr, nullptr, Qp, 0, lnum, -1);
    edge_kernel<<<296, 256, smemEdge>>>(ea, We1, be1, We2, be2, We3, be3, out + NODE_OUT_ELEMS);
}

// round 3
// speedup vs baseline: 1.7369x; 1.7369x over previous
#include <cuda_runtime.h>
#include <cuda_bf16.h>

// Problem constants (fixed by setup_inputs)
#define NN 50000
#define EE 400000
#define HD 128
#define FIN 16
#define EAD 8
#define MAX_LAYERS 6
#define NODE_OUT_ELEMS (NN * 2)

// ---------------- scratch (device globals; no allocation allowed) ----------------
__device__ float g_h[NN * HD];
__device__ float g_h2[NN * HD];   // fixup scratch (tiny use now)
__device__ float g_A[NN * HD];
__device__ float g_P[NN * HD];
__device__ float g_Q[NN * HD];
__device__ float g_U[HD * HD];
__device__ float g_V[HD * HD];
__device__ float g_c1[HD];

__device__ int g_src[EE];
__device__ int g_dst[EE];
__device__ int g_csrc[EE];     // CSR by dst: concatenated src ids
__device__ int g_deg[NN];
__device__ int g_rowptr[NN + 1];
__device__ int g_cursor[NN];
__device__ int g_zlist[NN];
__device__ int g_zcount;
__device__ int g_is64;
__device__ int g_bsum[128];
__device__ int g_boff[128];

// ---------------- f32x2 helpers ----------------
__device__ __forceinline__ unsigned long long pk2(float lo, float hi) {
    unsigned long long r;
    asm("mov.b64 %0, {%1, %2};" : "=l"(r) : "f"(lo), "f"(hi));
    return r;
}
__device__ __forceinline__ void upk2(unsigned long long v, float& lo, float& hi) {
    asm("mov.b64 {%0, %1}, %2;" : "=f"(lo), "=f"(hi) : "l"(v));
}
__device__ __forceinline__ void ffma2(unsigned long long& d, unsigned long long a, unsigned long long b) {
    asm("fma.rn.f32x2 %0, %1, %2, %0;" : "+l"(d) : "l"(a), "l"(b));
}

// ---------------- edge_index dtype detection ----------------
__global__ void detect_kernel(const long long* ei) {
    __shared__ int bad;
    if (threadIdx.x == 0) bad = 0;
    __syncthreads();
    for (int i = threadIdx.x; i < 1024; i += blockDim.x) {
        long long v = ei[i];
        if (v < 0 || v >= NN) bad = 1;
    }
    __syncthreads();
    if (threadIdx.x == 0) g_is64 = bad ? 0 : 1;
}

// ---------------- prep: convert + zero ----------------
__global__ void prep_kernel(const void* ei) {
    int idx = blockIdx.x * blockDim.x + threadIdx.x;
    int stride = gridDim.x * blockDim.x;
    int is64 = g_is64;
    const long long* p64 = (const long long*)ei;
    const int* p32 = (const int*)ei;
    for (int i = idx; i < EE; i += stride) {
        if (is64) {
            g_src[i] = (int)p64[i];
            g_dst[i] = (int)p64[EE + i];
        } else {
            g_src[i] = p32[i];
            g_dst[i] = p32[EE + i];
        }
        if (i < NN) g_deg[i] = 0;
    }
    if (idx == 0) g_zcount = 0;
}

__global__ void hist_kernel() {
    int idx = blockIdx.x * blockDim.x + threadIdx.x;
    int stride = gridDim.x * blockDim.x;
    for (int i = idx; i < EE; i += stride) atomicAdd(&g_deg[g_dst[i]], 1);
}

// ---------------- multi-block exclusive scan of g_deg -> g_rowptr ----------------
#define SCAN_B 512
#define SCAN_NB ((NN + SCAN_B - 1) / SCAN_B)   // 98

__global__ void scan1_kernel() {  // grid SCAN_NB, block 512
    __shared__ int wsum[16];
    int b = blockIdx.x, tid = threadIdx.x;
    int i = b * SCAN_B + tid;
    int v = (i < NN) ? g_deg[i] : 0;
    int lane = tid & 31, w = tid >> 5;
    int x = v;
#pragma unroll
    for (int off = 1; off < 32; off <<= 1) {
        int t = __shfl_up_sync(0xffffffffu, x, off);
        if (lane >= off) x += t;
    }
    if (lane == 31) wsum[w] = x;
    __syncthreads();
    if (w == 0) {
        int s = (lane < 16) ? wsum[lane] : 0;
#pragma unroll
        for (int off = 1; off < 16; off <<= 1) {
            int t = __shfl_up_sync(0xffffffffu, s, off);
            if (lane >= off) s += t;
        }
        if (lane < 16) wsum[lane] = s;
    }
    __syncthreads();
    int base = (w > 0) ? wsum[w - 1] : 0;
    int incl = base + x;
    if (i < NN) g_rowptr[i] = incl - v;  // block-local exclusive
    if (tid == SCAN_B - 1) g_bsum[b] = incl;
}

__global__ void scan2_kernel() {  // 1 block, 128 threads
    __shared__ int ws[4];
    int tid = threadIdx.x, lane = tid & 31, w = tid >> 5;
    int v = (tid < SCAN_NB) ? g_bsum[tid] : 0;
    int x = v;
#pragma unroll
    for (int off = 1; off < 32; off <<= 1) {
        int t = __shfl_up_sync(0xffffffffu, x, off);
        if (lane >= off) x += t;
    }
    if (lane == 31) ws[w] = x;
    __syncthreads();
    int base = 0;
    for (int q = 0; q < w; q++) base += ws[q];
    if (tid < SCAN_NB) g_boff[tid] = base + x - v;
}

__global__ void scan3_kernel() {  // grid SCAN_NB, block 512: finalize + nodeprep
    int b = blockIdx.x;
    int i = b * SCAN_B + threadIdx.x;
    if (i < NN) {
        int rp = g_rowptr[i] + g_boff[b];
        g_rowptr[i] = rp;
        g_cursor[i] = rp;
        if (g_deg[i] == 0) {
            int p = atomicAdd(&g_zcount, 1);
            g_zlist[p] = i;
        }
    }
    if (i == 0) g_rowptr[NN] = EE;
}

__global__ void scatter_kernel() {
    int idx = blockIdx.x * blockDim.x + threadIdx.x;
    int stride = gridDim.x * blockDim.x;
    for (int i = idx; i < EE; i += stride) {
        int d = g_dst[i];
        int pos = atomicAdd(&g_cursor[d], 1);
        g_csrc[pos] = g_src[i];
    }
}

// ---------------- combined layer weights: U = Wu_a + Wb@Wu_b, V = Wt@Wu_b ----------------
__global__ void uv_kernel(const float* __restrict__ Wmsg, const float* __restrict__ bmsg,
                          const float* __restrict__ Wupd, const float* __restrict__ bupd) {
    int k = blockIdx.x;   // 0..127
    int j = threadIdx.x;  // 0..127
    float u = Wupd[k * HD + j];
    float v = 0.f;
    for (int t = 0; t < HD; t++) {
        float wub = Wupd[(HD + t) * HD + j];
        u += Wmsg[(HD + k) * HD + t] * wub;   // Wb[k][t]
        v += Wmsg[k * HD + t] * wub;          // Wt[k][t]
    }
    g_U[k * HD + j] = u;
    g_V[k * HD + j] = v;
    if (k == 0) {
        float c = bupd[j];
        for (int t = 0; t < HD; t++) c += bmsg[t] * Wupd[(HD + t) * HD + j];
        g_c1[j] = c;
    }
}

// ---------------- encoder: h = x @ W_enc + b_enc ----------------
__global__ void encoder_kernel(const float* __restrict__ x, const float* __restrict__ Wenc,
                               const float* __restrict__ benc) {
    __shared__ float ws[FIN * HD];
    __shared__ float bs[HD];
    __shared__ float xs[FIN];
    int tid = threadIdx.x;  // 128
    for (int i = tid; i < FIN * HD; i += 128) ws[i] = Wenc[i];
    bs[tid] = benc[tid];
    __syncthreads();
    for (int v = blockIdx.x; v < NN; v += gridDim.x) {
        if (tid < FIN) xs[tid] = x[v * FIN + tid];
        __syncthreads();
        float acc = bs[tid];
#pragma unroll
        for (int k = 0; k < FIN; k++) acc += xs[k] * ws[k * HD + tid];
        g_h[v * HD + tid] = acc;
        __syncthreads();
    }
}

// ---------------- aggregation: A[v] = mean over in-edges of h[src] ----------------
__global__ void agg_kernel(const int* __restrict__ lnum, int layer) {
    if (layer >= *lnum) return;
    int j = threadIdx.x;  // 128
    for (int v = blockIdx.x; v < NN; v += gridDim.x) {
        int s0 = g_rowptr[v], s1 = g_rowptr[v + 1];
        float acc = 0.f;
        for (int idx = s0; idx < s1; idx++) acc += g_h[g_csrc[idx] * HD + j];
        int dg = s1 - s0;
        float dd = dg > 0 ? (float)dg : 1.f;
        g_A[v * HD + j] = acc / dd;
    }
}

// ---------------- generic C = act(X1@W1 [+ X2@W2] + bias), W [128,128], C [NN,128] ----------
// f32x2 packed inner product; duplicated X in smem. In-place-safe (block writes only
// its own 64 rows, after all reads). gateDeg: skip rows with deg==0 (fixup handles them).
__global__ void gemm_kernel(const float* __restrict__ X1, const float* __restrict__ W1,
                            const float* __restrict__ X2, const float* __restrict__ W2,
                            const float* __restrict__ bias, float* __restrict__ C,
                            int doRelu, int gateDeg, const int* __restrict__ lnum, int layer) {
    if (layer >= 0 && layer >= *lnum) return;
    __shared__ unsigned long long Xs[64 * 8];  // duplicated (x,x) pairs, 4 KB
    int tid = threadIdx.x;       // 256
    int tx = tid & 31, ty = tid >> 5;
    int row0 = blockIdx.x * 64;
    int c0 = tx * 4;
    unsigned long long accp[8][2];
    {
        float b0 = 0.f, b1v = 0.f, b2v = 0.f, b3v = 0.f;
        if (bias) {
            float4 b = *(const float4*)(bias + c0);
            b0 = b.x; b1v = b.y; b2v = b.z; b3v = b.w;
        }
        unsigned long long p0 = pk2(b0, b1v), p1 = pk2(b2v, b3v);
#pragma unroll
        for (int i = 0; i < 8; i++) { accp[i][0] = p0; accp[i][1] = p1; }
    }
    const float* X = X1;
    const float* W = W1;
    for (int pass = 0; pass < 2; pass++) {
        if (pass == 1) {
            if (!X2) break;
            X = X2; W = W2;
        }
        for (int k0 = 0; k0 < HD; k0 += 8) {
            {
                int e = tid, rl = e >> 3, kk = e & 7, r = row0 + rl;
                float v = (r < NN) ? X[r * HD + k0 + kk] : 0.f;
                Xs[e] = pk2(v, v);
                e = tid + 256; rl = e >> 3; kk = e & 7; r = row0 + rl;
                v = (r < NN) ? X[r * HD + k0 + kk] : 0.f;
                Xs[e] = pk2(v, v);
            }
            __syncthreads();
#pragma unroll
            for (int kk = 0; kk < 8; kk++) {
                ulonglong2 w = *(const ulonglong2*)(W + (k0 + kk) * HD + c0);
#pragma unroll
                for (int i = 0; i < 8; i++) {
                    unsigned long long xv = Xs[(i * 8 + ty) * 8 + kk];
                    ffma2(accp[i][0], xv, w.x);
                    ffma2(accp[i][1], xv, w.y);
                }
            }
            __syncthreads();
        }
    }
#pragma unroll
    for (int i = 0; i < 8; i++) {
        int r = row0 + i * 8 + ty;
        if (r < NN && (!gateDeg || g_deg[r] != 0)) {
            float4 o;
            upk2(accp[i][0], o.x, o.y);
            upk2(accp[i][1], o.z, o.w);
            if (doRelu) {
                o.x = fmaxf(o.x, 0.f); o.y = fmaxf(o.y, 0.f);
                o.z = fmaxf(o.z, 0.f); o.w = fmaxf(o.w, 0.f);
            }
            *(float4*)(C + r * HD + c0) = o;
        }
    }
}

// ---------------- fixup for zero-in-degree nodes: h = relu(h@Wu_a + b_upd), in place ----
__global__ void fixup_kernel(const float* __restrict__ Wupd, const float* __restrict__ bupd,
                             const int* __restrict__ lnum, int layer) {
    if (layer >= *lnum) return;
    __shared__ float hs[HD];
    int tid = threadIdx.x;  // 128
    int zc = g_zcount;
    for (int zi = blockIdx.x; zi < zc; zi += gridDim.x) {
        int v = g_zlist[zi];
        hs[tid] = g_h[v * HD + tid];
        __syncthreads();
        float acc = bupd[tid];
#pragma unroll 8
        for (int k = 0; k < HD; k++) acc += hs[k] * Wupd[k * HD + tid];
        __syncthreads();
        g_h[v * HD + tid] = fmaxf(acc, 0.f);
        __syncthreads();
    }
}

// ---------------- fused node head: out = relu(h@Wn1+bn1)@Wn2+bn2 ----------------
// Block: 256 threads, 128 rows, full 64-col stage1 in registers, stage2 via shuffle.
__global__ void nodehead_kernel(const float* __restrict__ Wn1, const float* __restrict__ bn1,
                                const float* __restrict__ Wn2, const float* __restrict__ bn2,
                                float* __restrict__ out) {
    __shared__ unsigned long long Xs[128 * 8];  // duplicated pairs, 8 KB
    int tid = threadIdx.x;       // 256
    int tx = tid & 15, ty = tid >> 4;   // tx: col group (16), ty: row group (16)
    int row0 = blockIdx.x * 128;
    int c0 = tx * 4;
    unsigned long long accp[8][2];
    {
        float4 b = *(const float4*)(bn1 + c0);
        unsigned long long p0 = pk2(b.x, b.y), p1 = pk2(b.z, b.w);
#pragma unroll
        for (int i = 0; i < 8; i++) { accp[i][0] = p0; accp[i][1] = p1; }
    }
    for (int k0 = 0; k0 < HD; k0 += 8) {
#pragma unroll
        for (int q = 0; q < 4; q++) {
            int e = tid + 256 * q;
            int rl = e >> 3, kk = e & 7, r = row0 + rl;
            float v = (r < NN) ? g_h[r * HD + k0 + kk] : 0.f;
            Xs[e] = pk2(v, v);
        }
        __syncthreads();
#pragma unroll
        for (int kk = 0; kk < 8; kk++) {
            ulonglong2 w = *(const ulonglong2*)(Wn1 + (k0 + kk) * 64 + c0);
#pragma unroll
            for (int i = 0; i < 8; i++) {
                unsigned long long xv = Xs[(i * 16 + ty) * 8 + kk];
                ffma2(accp[i][0], xv, w.x);
                ffma2(accp[i][1], xv, w.y);
            }
        }
        __syncthreads();
    }
    // stage 2: per row, out[o] = sum_j relu(t[j]) * Wn2[j][o] + bn2[o]
    float2 w2a = *(const float2*)(Wn2 + (c0 + 0) * 2);
    float2 w2b = *(const float2*)(Wn2 + (c0 + 1) * 2);
    float2 w2c = *(const float2*)(Wn2 + (c0 + 2) * 2);
    float2 w2d = *(const float2*)(Wn2 + (c0 + 3) * 2);
    float2 b2v = *(const float2*)(bn2);
#pragma unroll
    for (int i = 0; i < 8; i++) {
        float t0, t1, t2, t3;
        upk2(accp[i][0], t0, t1);
        upk2(accp[i][1], t2, t3);
        t0 = fmaxf(t0, 0.f); t1 = fmaxf(t1, 0.f);
        t2 = fmaxf(t2, 0.f); t3 = fmaxf(t3, 0.f);
        float p0 = t0 * w2a.x + t1 * w2b.x + t2 * w2c.x + t3 * w2d.x;
        float p1 = t0 * w2a.y + t1 * w2b.y + t2 * w2c.y + t3 * w2d.y;
#pragma unroll
        for (int off = 8; off >= 1; off >>= 1) {
            p0 += __shfl_xor_sync(0xffffffffu, p0, off);
            p1 += __shfl_xor_sync(0xffffffffu, p1, off);
        }
        int r = row0 + i * 16 + ty;
        if (tx == 0 && r < NN) {
            float2 o; o.x = p0 + b2v.x; o.y = p1 + b2v.y;
            *(float2*)(out + r * 2) = o;
        }
    }
}

// ---------------- fused edge head ----------------
// t = relu(P[src] + Q[dst] + ea@We1c + be1); u = relu(t@We2 + be2); out = u@We3 + be3
#define SMEM_EDGE_FLOATS (1024 + 8192 + 384 + 128 + 64 + 8 + 128 * 68 + 64 * 64 + 512 + 64)
__global__ void edge_kernel(const float* __restrict__ ea, const float* __restrict__ We1,
                            const float* __restrict__ be1, const float* __restrict__ We2,
                            const float* __restrict__ be2, const float* __restrict__ We3,
                            const float* __restrict__ be3, float* __restrict__ out) {
    extern __shared__ float sm[];
    float* wc = sm;              // 8x128 = 1024
    float* w2 = wc + 1024;       // 128x64 = 8192
    float* w3 = w2 + 8192;       // 64x6 = 384
    float* b1 = w3 + 384;        // 128
    float* b2 = b1 + 128;        // 64
    float* b3 = b2 + 64;         // 8 (padded)
    float* ts = b3 + 8;          // 128 x 68 (padded stride), 16B-aligned base
    float* us = ts + 128 * 68;   // 64 x 64 = 4096
    float* eas = us + 4096;      // 64 x 8 = 512
    int* ssrc = (int*)(eas + 512);  // 64 ints in trailing 64-float block
    int tid = threadIdx.x;  // 256

    for (int i = tid; i < 1024; i += 256) wc[i] = We1[256 * HD + i];
    for (int i = tid; i < 8192; i += 256) w2[i] = We2[i];
    for (int i = tid; i < 384; i += 256) w3[i] = We3[i];
    if (tid < 128) b1[tid] = be1[tid];
    if (tid < 64) b2[tid] = be2[tid];
    if (tid < 6) b3[tid] = be3[tid];
    __syncthreads();

    int eb = (tid & 15) * 4;
    int jb = (tid >> 4) * 4;

    for (int e0 = blockIdx.x * 64; e0 < EE; e0 += gridDim.x * 64) {
        if (tid < 64) {
            int e = e0 + tid;
            ssrc[tid] = (e < EE) ? g_src[e] : 0;
            int d = (e < EE) ? g_dst[e] : 0;
            ((int*)ts)[(tid >> 2) * 68 + 64 + (tid & 3)] = d;  // pad slots rows 0..15
        }
        for (int idx = tid; idx < 512; idx += 256) {
            int el = idx >> 3;
            int e = e0 + el;
            eas[idx] = (e < EE) ? ea[e * EAD + (idx & 7)] : 0.f;
        }
        __syncthreads();
        // phase 1: t[j][el]
        for (int r = 0; r < 32; r++) {
            int idx = tid + 256 * r;
            int el = idx >> 7, j = idx & 127;
            int e = e0 + el;
            float acc = b1[j];
#pragma unroll
            for (int k = 0; k < EAD; k++) acc += eas[el * 8 + k] * wc[k * HD + j];
            if (e < EE) {
                int s = ssrc[el];
                int d = ((int*)ts)[(el >> 2) * 68 + 64 + (el & 3)];
                acc += g_P[s * HD + j] + g_Q[d * HD + j];
            }
            ts[j * 68 + el] = fmaxf(acc, 0.f);
        }
        __syncthreads();
        // phase 2: u = relu(t@We2 + be2) — f32x2 packed over edge pairs
        unsigned long long ap[2][4];
#pragma unroll
        for (int ji = 0; ji < 4; ji++) {
            float b = b2[jb + ji];
            unsigned long long bp = pk2(b, b);
            ap[0][ji] = bp; ap[1][ji] = bp;
        }
#pragma unroll 8
        for (int k = 0; k < HD; k++) {
            ulonglong2 tv = *(const ulonglong2*)(ts + k * 68 + eb);
            float4 wv = *(const float4*)(w2 + k * 64 + jb);
            unsigned long long wp0 = pk2(wv.x, wv.x);
            unsigned long long wp1 = pk2(wv.y, wv.y);
            unsigned long long wp2 = pk2(wv.z, wv.z);
            unsigned long long wp3 = pk2(wv.w, wv.w);
            ffma2(ap[0][0], tv.x, wp0); ffma2(ap[1][0], tv.y, wp0);
            ffma2(ap[0][1], tv.x, wp1); ffma2(ap[1][1], tv.y, wp1);
            ffma2(ap[0][2], tv.x, wp2); ffma2(ap[1][2], tv.y, wp2);
            ffma2(ap[0][3], tv.x, wp3); ffma2(ap[1][3], tv.y, wp3);
        }
        {
            float f[4][4];  // [edge-in-quad][ji]
#pragma unroll
            for (int ji = 0; ji < 4; ji++) {
                upk2(ap[0][ji], f[0][ji], f[1][ji]);
                upk2(ap[1][ji], f[2][ji], f[3][ji]);
            }
#pragma unroll
            for (int ei = 0; ei < 4; ei++) {
                float4 o;
                o.x = fmaxf(f[ei][0], 0.f); o.y = fmaxf(f[ei][1], 0.f);
                o.z = fmaxf(f[ei][2], 0.f); o.w = fmaxf(f[ei][3], 0.f);
                *(float4*)(us + (eb + ei) * 64 + jb) = o;
            }
        }
        __syncthreads();
        // phase 3: out = u@We3 + be3
        for (int oi = tid; oi < 384; oi += 256) {
            int el = oi / 6, o = oi % 6;
            float a0 = 0.f, a1 = 0.f, a2 = 0.f, a3 = 0.f;
#pragma unroll
            for (int j = 0; j < 64; j += 4) {
                a0 += us[el * 64 + j] * w3[j * 6 + o];
                a1 += us[el * 64 + j + 1] * w3[(j + 1) * 6 + o];
                a2 += us[el * 64 + j + 2] * w3[(j + 2) * 6 + o];
                a3 += us[el * 64 + j + 3] * w3[(j + 3) * 6 + o];
            }
            int e = e0 + el;
            if (e < EE) out[e * 6 + o] = b3[o] + a0 + a1 + a2 + a3;
        }
        __syncthreads();
    }
}

// ---------------- launch ----------------
extern "C" void kernel_launch(void* const* d_in, const int* in_sizes, int n_in,
                              void* d_out, int out_size) {
    const float* x    = (const float*)d_in[0];
    const void*  ei   = d_in[1];
    const float* ea   = (const float*)d_in[2];
    const int*   lnum = (const int*)d_in[3];
    const float* Wenc = (const float*)d_in[4];
    const float* benc = (const float*)d_in[5];
    const float* Wmsg = (const float*)d_in[6];
    const float* bmsg = (const float*)d_in[7];
    const float* Wupd = (const float*)d_in[8];
    const float* bupd = (const float*)d_in[9];
    const float* Wn1  = (const float*)d_in[10];
    const float* bn1  = (const float*)d_in[11];
    const float* Wn2  = (const float*)d_in[12];
    const float* bn2  = (const float*)d_in[13];
    const float* We1  = (const float*)d_in[14];
    const float* be1  = (const float*)d_in[15];
    const float* We2  = (const float*)d_in[16];
    const float* be2  = (const float*)d_in[17];
    const float* We3  = (const float*)d_in[18];
    const float* be3  = (const float*)d_in[19];
    float* out = (float*)d_out;

    float *hp, *Ap, *Pp, *Qp, *Up, *Vp, *c1p;
    cudaGetSymbolAddress((void**)&hp,  g_h);
    cudaGetSymbolAddress((void**)&Ap,  g_A);
    cudaGetSymbolAddress((void**)&Pp,  g_P);
    cudaGetSymbolAddress((void**)&Qp,  g_Q);
    cudaGetSymbolAddress((void**)&Up,  g_U);
    cudaGetSymbolAddress((void**)&Vp,  g_V);
    cudaGetSymbolAddress((void**)&c1p, g_c1);

    const int smemEdge = SMEM_EDGE_FLOATS * 4;
    cudaFuncSetAttribute(edge_kernel, cudaFuncAttributeMaxDynamicSharedMemorySize, smemEdge);

    detect_kernel<<<1, 256>>>((const long long*)ei);
    prep_kernel<<<2048, 256>>>(ei);
    hist_kernel<<<2048, 256>>>();
    scan1_kernel<<<SCAN_NB, SCAN_B>>>();
    scan2_kernel<<<1, 128>>>();
    scan3_kernel<<<SCAN_NB, SCAN_B>>>();
    scatter_kernel<<<2048, 256>>>();
    uv_kernel<<<128, 128>>>(Wmsg, bmsg, Wupd, bupd);
    encoder_kernel<<<1184, 128>>>(x, Wenc, benc);

    const int gemmGrid = (NN + 63) / 64;  // 782
    for (int L = 0; L < MAX_LAYERS; L++) {
        agg_kernel<<<2048, 128>>>(lnum, L);
        // in-place: h = relu(h@U + A@V + c1), rows with deg==0 skipped
        gemm_kernel<<<gemmGrid, 256>>>(hp, Up, Ap, Vp, c1p, hp, 1, 1, lnum, L);
        fixup_kernel<<<64, 128>>>(Wupd, bupd, lnum, L);
    }

    nodehead_kernel<<<(NN + 127) / 128, 256>>>(Wn1, bn1, Wn2, bn2, out);
    // P = h @ We1[0:128], Q = h @ We1[128:256]
    gemm_kernel<<<gemmGrid, 256>>>(hp, We1, nullptr, nullptr, nullptr, Pp, 0, 0, lnum, -1);
    gemm_kernel<<<gemmGrid, 256>>>(hp, We1 + 128 * HD, nullptr, nullptr, nullptr, Qp, 0, 0, lnum, -1);
    edge_kernel<<<296, 256, smemEdge>>>(ea, We1, be1, We2, be2, We3, be3, out + NODE_OUT_ELEMS);
}

// round 4
// speedup vs baseline: 1.9302x; 1.1112x over previous
#include <cuda_runtime.h>
#include <cuda_bf16.h>

// Problem constants (fixed by setup_inputs)
#define NN 50000
#define EE 400000
#define HD 128
#define FIN 16
#define EAD 8
#define MAX_LAYERS 6
#define NODE_OUT_ELEMS (NN * 2)

typedef unsigned long long ull;

// ---------------- scratch (device globals; no allocation allowed) ----------------
__device__ float g_h[NN * HD];
__device__ float g_h2[NN * HD];
__device__ float g_P[NN * HD];
__device__ float g_Q[NN * HD];
__device__ float g_U[HD * HD];
__device__ float g_V[HD * HD];
__device__ float g_c1[HD];

__device__ int g_src[EE];
__device__ int g_dst[EE];
__device__ int g_csrc[EE];     // CSR by dst: concatenated src ids
__device__ int g_deg[NN];
__device__ int g_rowptr[NN + 1];
__device__ int g_cursor[NN];
__device__ int g_zlist[NN];
__device__ int g_zcount;
__device__ int g_is64;
__device__ int g_bsum[128];
__device__ int g_boff[128];

// ---------------- f32x2 helpers ----------------
__device__ __forceinline__ ull pk2(float lo, float hi) {
    ull r;
    asm("mov.b64 %0, {%1, %2};" : "=l"(r) : "f"(lo), "f"(hi));
    return r;
}
__device__ __forceinline__ void upk2(ull v, float& lo, float& hi) {
    asm("mov.b64 {%0, %1}, %2;" : "=f"(lo), "=f"(hi) : "l"(v));
}
__device__ __forceinline__ void ffma2(ull& d, ull a, ull b) {
    asm("fma.rn.f32x2 %0, %1, %2, %0;" : "+l"(d) : "l"(a), "l"(b));
}

// ---------------- detect dtype + zero deg ----------------
__global__ void detect_kernel(const long long* ei) {
    int idx = blockIdx.x * blockDim.x + threadIdx.x;
    int stride = gridDim.x * blockDim.x;
    for (int i = idx; i < NN; i += stride) g_deg[i] = 0;
    if (idx == 0) g_zcount = 0;
    if (blockIdx.x == 0) {
        __shared__ int bad;
        if (threadIdx.x == 0) bad = 0;
        __syncthreads();
        for (int i = threadIdx.x; i < 1024; i += blockDim.x) {
            long long v = ei[i];
            if (v < 0 || v >= NN) bad = 1;
        }
        __syncthreads();
        if (threadIdx.x == 0) g_is64 = bad ? 0 : 1;
    }
}

// ---------------- prep: convert + histogram ----------------
__global__ void prep_kernel(const void* ei) {
    int idx = blockIdx.x * blockDim.x + threadIdx.x;
    int stride = gridDim.x * blockDim.x;
    int is64 = g_is64;
    const long long* p64 = (const long long*)ei;
    const int* p32 = (const int*)ei;
    for (int i = idx; i < EE; i += stride) {
        int s, d;
        if (is64) {
            s = (int)p64[i];
            d = (int)p64[EE + i];
        } else {
            s = p32[i];
            d = p32[EE + i];
        }
        g_src[i] = s;
        g_dst[i] = d;
        atomicAdd(&g_deg[d], 1);
    }
}

// ---------------- multi-block exclusive scan of g_deg -> g_rowptr ----------------
#define SCAN_B 512
#define SCAN_NB ((NN + SCAN_B - 1) / SCAN_B)   // 98

__global__ void scan1_kernel() {
    __shared__ int wsum[16];
    int b = blockIdx.x, tid = threadIdx.x;
    int i = b * SCAN_B + tid;
    int v = (i < NN) ? g_deg[i] : 0;
    int lane = tid & 31, w = tid >> 5;
    int x = v;
#pragma unroll
    for (int off = 1; off < 32; off <<= 1) {
        int t = __shfl_up_sync(0xffffffffu, x, off);
        if (lane >= off) x += t;
    }
    if (lane == 31) wsum[w] = x;
    __syncthreads();
    if (w == 0) {
        int s = (lane < 16) ? wsum[lane] : 0;
#pragma unroll
        for (int off = 1; off < 16; off <<= 1) {
            int t = __shfl_up_sync(0xffffffffu, s, off);
            if (lane >= off) s += t;
        }
        if (lane < 16) wsum[lane] = s;
    }
    __syncthreads();
    int base = (w > 0) ? wsum[w - 1] : 0;
    int incl = base + x;
    if (i < NN) g_rowptr[i] = incl - v;  // block-local exclusive
    if (tid == SCAN_B - 1) g_bsum[b] = incl;
}

__global__ void scan2_kernel() {
    __shared__ int ws[4];
    int tid = threadIdx.x, lane = tid & 31, w = tid >> 5;
    int v = (tid < SCAN_NB) ? g_bsum[tid] : 0;
    int x = v;
#pragma unroll
    for (int off = 1; off < 32; off <<= 1) {
        int t = __shfl_up_sync(0xffffffffu, x, off);
        if (lane >= off) x += t;
    }
    if (lane == 31) ws[w] = x;
    __syncthreads();
    int base = 0;
    for (int q = 0; q < w; q++) base += ws[q];
    if (tid < SCAN_NB) g_boff[tid] = base + x - v;
}

__global__ void scan3_kernel() {
    int b = blockIdx.x;
    int i = b * SCAN_B + threadIdx.x;
    if (i < NN) {
        int rp = g_rowptr[i] + g_boff[b];
        g_rowptr[i] = rp;
        g_cursor[i] = rp;
        if (g_deg[i] == 0) {
            int p = atomicAdd(&g_zcount, 1);
            g_zlist[p] = i;
        }
    }
    if (i == 0) g_rowptr[NN] = EE;
}

__global__ void scatter_kernel() {
    int idx = blockIdx.x * blockDim.x + threadIdx.x;
    int stride = gridDim.x * blockDim.x;
    for (int i = idx; i < EE; i += stride) {
        int d = g_dst[i];
        int pos = atomicAdd(&g_cursor[d], 1);
        g_csrc[pos] = g_src[i];
    }
}

// ---------------- combined layer weights: U = Wu_a + Wb@Wu_b, V = Wt@Wu_b ----------------
__global__ void uv_kernel(const float* __restrict__ Wmsg, const float* __restrict__ bmsg,
                          const float* __restrict__ Wupd, const float* __restrict__ bupd) {
    int k = blockIdx.x;   // 0..127
    int j = threadIdx.x;  // 0..127
    float u = Wupd[k * HD + j];
    float v = 0.f;
    for (int t = 0; t < HD; t++) {
        float wub = Wupd[(HD + t) * HD + j];
        u += Wmsg[(HD + k) * HD + t] * wub;   // Wb[k][t]
        v += Wmsg[k * HD + t] * wub;          // Wt[k][t]
    }
    g_U[k * HD + j] = u;
    g_V[k * HD + j] = v;
    if (k == 0) {
        float c = bupd[j];
        for (int t = 0; t < HD; t++) c += bmsg[t] * Wupd[(HD + t) * HD + j];
        g_c1[j] = c;
    }
}

// ---------------- encoder: h = x @ W_enc + b_enc ----------------
__global__ void encoder_kernel(const float* __restrict__ x, const float* __restrict__ Wenc,
                               const float* __restrict__ benc) {
    __shared__ float ws[FIN * HD];
    __shared__ float bs[HD];
    __shared__ float xs[FIN];
    int tid = threadIdx.x;  // 128
    for (int i = tid; i < FIN * HD; i += 128) ws[i] = Wenc[i];
    bs[tid] = benc[tid];
    __syncthreads();
    for (int v = blockIdx.x; v < NN; v += gridDim.x) {
        if (tid < FIN) xs[tid] = x[v * FIN + tid];
        __syncthreads();
        float acc = bs[tid];
#pragma unroll
        for (int k = 0; k < FIN; k++) acc += xs[k] * ws[k * HD + tid];
        g_h[v * HD + tid] = acc;
        __syncthreads();
    }
}

// ---------------- fused layer: agg + h' = relu(h@U + A@V + c1) ----------------
// 256 threads, 64 nodes/block. Warp-uniform weight broadcast; FFMA2 inner.
#define LAYER_SMEM_FLOATS (8448 + 8448 + 2048)
__global__ void layer_kernel(const float* __restrict__ hcur, float* __restrict__ hnext,
                             const int* __restrict__ lnum, int layer) {
    if (layer >= *lnum) return;
    extern __shared__ float lsm[];
    float* Hst = lsm;            // [k 128][r 64] stride 66
    float* Ast = Hst + 8448;     // [k 128][r 64] stride 66
    float* Ws  = Ast + 8448;     // [16][128] chunk
    int tid = threadIdx.x;
    int warp = tid >> 5, lane = tid & 31;
    int row0 = blockIdx.x * 64;

    // load Hst transposed
#pragma unroll 4
    for (int q = 0; q < 32; q++) {
        int e = tid + 256 * q;
        int r = e >> 7, k = e & 127;
        int gr = row0 + r;
        Hst[k * 66 + r] = (gr < NN) ? hcur[gr * HD + k] : 0.f;
    }

    // stage A: mean-aggregate into Ast (transposed)
    for (int n = warp; n < 64; n += 8) {
        int v = row0 + n;
        float4 a0 = make_float4(0.f, 0.f, 0.f, 0.f);
        float4 a1 = make_float4(0.f, 0.f, 0.f, 0.f);
        int dg = 0;
        if (v < NN) {
            int s0 = g_rowptr[v], s1 = g_rowptr[v + 1];
            dg = s1 - s0;
            int idx = s0;
            for (; idx + 1 < s1; idx += 2) {
                int sA = g_csrc[idx], sB = g_csrc[idx + 1];
                float4 hA = *(const float4*)(hcur + sA * HD + lane * 4);
                float4 hB = *(const float4*)(hcur + sB * HD + lane * 4);
                a0.x += hA.x; a0.y += hA.y; a0.z += hA.z; a0.w += hA.w;
                a1.x += hB.x; a1.y += hB.y; a1.z += hB.z; a1.w += hB.w;
            }
            if (idx < s1) {
                int sA = g_csrc[idx];
                float4 hA = *(const float4*)(hcur + sA * HD + lane * 4);
                a0.x += hA.x; a0.y += hA.y; a0.z += hA.z; a0.w += hA.w;
            }
        }
        float inv = 1.f / (float)(dg > 0 ? dg : 1);
        int j0 = lane * 4;
        Ast[(j0 + 0) * 66 + n] = (a0.x + a1.x) * inv;
        Ast[(j0 + 1) * 66 + n] = (a0.y + a1.y) * inv;
        Ast[(j0 + 2) * 66 + n] = (a0.z + a1.z) * inv;
        Ast[(j0 + 3) * 66 + n] = (a0.w + a1.w) * inv;
    }
    __syncthreads();

    int jb = warp * 16;
    ull acc[2][8];
    {
        const ulonglong2* cp = (const ulonglong2*)(g_c1 + jb);
        ulonglong2 q0 = cp[0], q1 = cp[1], q2 = cp[2], q3 = cp[3];
        acc[0][0] = q0.x; acc[0][1] = q0.y; acc[0][2] = q1.x; acc[0][3] = q1.y;
        acc[0][4] = q2.x; acc[0][5] = q2.y; acc[0][6] = q3.x; acc[0][7] = q3.y;
#pragma unroll
        for (int i = 0; i < 8; i++) acc[1][i] = acc[0][i];
    }
    for (int pass = 0; pass < 2; pass++) {
        const float* Wg = pass ? g_V : g_U;
        const float* Xt = pass ? Ast : Hst;
        for (int c = 0; c < 8; c++) {
#pragma unroll
            for (int q = 0; q < 8; q++) Ws[tid + 256 * q] = Wg[c * 2048 + tid + 256 * q];
            __syncthreads();
#pragma unroll
            for (int kk = 0; kk < 16; kk++) {
                const float* wr = Ws + kk * 128 + jb;
                ulonglong2 wA = *(const ulonglong2*)(wr);
                ulonglong2 wB = *(const ulonglong2*)(wr + 4);
                ulonglong2 wC = *(const ulonglong2*)(wr + 8);
                ulonglong2 wD = *(const ulonglong2*)(wr + 12);
                float2 xv = *(const float2*)(Xt + (c * 16 + kk) * 66 + lane * 2);
                ull x0 = pk2(xv.x, xv.x), x1 = pk2(xv.y, xv.y);
                ffma2(acc[0][0], x0, wA.x); ffma2(acc[0][1], x0, wA.y);
                ffma2(acc[0][2], x0, wB.x); ffma2(acc[0][3], x0, wB.y);
                ffma2(acc[0][4], x0, wC.x); ffma2(acc[0][5], x0, wC.y);
                ffma2(acc[0][6], x0, wD.x); ffma2(acc[0][7], x0, wD.y);
                ffma2(acc[1][0], x1, wA.x); ffma2(acc[1][1], x1, wA.y);
                ffma2(acc[1][2], x1, wB.x); ffma2(acc[1][3], x1, wB.y);
                ffma2(acc[1][4], x1, wC.x); ffma2(acc[1][5], x1, wC.y);
                ffma2(acc[1][6], x1, wD.x); ffma2(acc[1][7], x1, wD.y);
            }
            __syncthreads();
        }
    }
#pragma unroll
    for (int rr = 0; rr < 2; rr++) {
        int r = row0 + lane * 2 + rr;
        if (r < NN && g_deg[r] != 0) {
            float f[16];
#pragma unroll
            for (int i = 0; i < 8; i++) upk2(acc[rr][i], f[2 * i], f[2 * i + 1]);
            float4* dst = (float4*)(hnext + r * HD + jb);
#pragma unroll
            for (int qq = 0; qq < 4; qq++) {
                float4 o;
                o.x = fmaxf(f[4 * qq + 0], 0.f); o.y = fmaxf(f[4 * qq + 1], 0.f);
                o.z = fmaxf(f[4 * qq + 2], 0.f); o.w = fmaxf(f[4 * qq + 3], 0.f);
                dst[qq] = o;
            }
        }
    }
}

// ---------------- fixup for zero-in-degree nodes: hnext = relu(hcur@Wu_a + b_upd) ----
__global__ void fixup_kernel(const float* __restrict__ Wupd, const float* __restrict__ bupd,
                             const int* __restrict__ lnum, int layer,
                             const float* __restrict__ hcur, float* __restrict__ hnext) {
    if (layer >= *lnum) return;
    __shared__ float hs[HD];
    int tid = threadIdx.x;  // 128
    int zc = g_zcount;
    for (int zi = blockIdx.x; zi < zc; zi += gridDim.x) {
        int v = g_zlist[zi];
        hs[tid] = hcur[v * HD + tid];
        __syncthreads();
        float acc = bupd[tid];
#pragma unroll 8
        for (int k = 0; k < HD; k++) acc += hs[k] * Wupd[k * HD + tid];
        hnext[v * HD + tid] = fmaxf(acc, 0.f);
        __syncthreads();
    }
}

// ---------------- fused P/Q: P = h@We1[0:128], Q = h@We1[128:256] ----------------
__global__ void pq_kernel(const float* __restrict__ We1, const int* __restrict__ lnum) {
    const float* X = ((*lnum) & 1) ? g_h2 : g_h;
    __shared__ float Hst[8448];   // [k 128][r 64] stride 66
    __shared__ float Ws[2048];
    int tid = threadIdx.x;
    int warp = tid >> 5, lane = tid & 31;
    int row0 = blockIdx.x * 64;
#pragma unroll 4
    for (int q = 0; q < 32; q++) {
        int e = tid + 256 * q;
        int r = e >> 7, k = e & 127;
        int gr = row0 + r;
        Hst[k * 66 + r] = (gr < NN) ? X[gr * HD + k] : 0.f;
    }
    __syncthreads();
    int jb = warp * 16;
    for (int m = 0; m < 2; m++) {
        const float* Wg = We1 + m * 128 * HD;
        float* C = m ? g_Q : g_P;
        ull acc[2][8];
        ull z = pk2(0.f, 0.f);
#pragma unroll
        for (int i = 0; i < 8; i++) { acc[0][i] = z; acc[1][i] = z; }
        for (int c = 0; c < 8; c++) {
#pragma unroll
            for (int q = 0; q < 8; q++) Ws[tid + 256 * q] = Wg[c * 2048 + tid + 256 * q];
            __syncthreads();
#pragma unroll
            for (int kk = 0; kk < 16; kk++) {
                const float* wr = Ws + kk * 128 + jb;
                ulonglong2 wA = *(const ulonglong2*)(wr);
                ulonglong2 wB = *(const ulonglong2*)(wr + 4);
                ulonglong2 wC = *(const ulonglong2*)(wr + 8);
                ulonglong2 wD = *(const ulonglong2*)(wr + 12);
                float2 xv = *(const float2*)(Hst + (c * 16 + kk) * 66 + lane * 2);
                ull x0 = pk2(xv.x, xv.x), x1 = pk2(xv.y, xv.y);
                ffma2(acc[0][0], x0, wA.x); ffma2(acc[0][1], x0, wA.y);
                ffma2(acc[0][2], x0, wB.x); ffma2(acc[0][3], x0, wB.y);
                ffma2(acc[0][4], x0, wC.x); ffma2(acc[0][5], x0, wC.y);
                ffma2(acc[0][6], x0, wD.x); ffma2(acc[0][7], x0, wD.y);
                ffma2(acc[1][0], x1, wA.x); ffma2(acc[1][1], x1, wA.y);
                ffma2(acc[1][2], x1, wB.x); ffma2(acc[1][3], x1, wB.y);
                ffma2(acc[1][4], x1, wC.x); ffma2(acc[1][5], x1, wC.y);
                ffma2(acc[1][6], x1, wD.x); ffma2(acc[1][7], x1, wD.y);
            }
            __syncthreads();
        }
#pragma unroll
        for (int rr = 0; rr < 2; rr++) {
            int r = row0 + lane * 2 + rr;
            if (r < NN) {
                float f[16];
#pragma unroll
                for (int i = 0; i < 8; i++) upk2(acc[rr][i], f[2 * i], f[2 * i + 1]);
                float4* dst = (float4*)(C + r * HD + jb);
#pragma unroll
                for (int qq = 0; qq < 4; qq++) {
                    float4 o;
                    o.x = f[4 * qq + 0]; o.y = f[4 * qq + 1];
                    o.z = f[4 * qq + 2]; o.w = f[4 * qq + 3];
                    dst[qq] = o;
                }
            }
        }
    }
}

// ---------------- node head ----------------
#define NH_SMEM_FLOATS (8448 + 8192 + 4352 + 128)
__global__ void nodehead_kernel(const float* __restrict__ Wn1, const float* __restrict__ bn1,
                                const float* __restrict__ Wn2, const float* __restrict__ bn2,
                                float* __restrict__ out, const int* __restrict__ lnum) {
    const float* X = ((*lnum) & 1) ? g_h2 : g_h;
    extern __shared__ float nsm[];
    float* Hst = nsm;             // [k 128][r 64] stride 66
    float* W1s = Hst + 8448;      // 128*64
    float* tsb = W1s + 8192;      // [r 64][j 64] stride 68
    float* W2s = tsb + 4352;      // 64*2
    int tid = threadIdx.x;
    int warp = tid >> 5, lane = tid & 31;
    int row0 = blockIdx.x * 64;
#pragma unroll 4
    for (int q = 0; q < 32; q++) {
        int e = tid + 256 * q;
        int r = e >> 7, k = e & 127;
        int gr = row0 + r;
        Hst[k * 66 + r] = (gr < NN) ? X[gr * HD + k] : 0.f;
    }
    for (int i = tid; i < 8192; i += 256) W1s[i] = Wn1[i];
    if (tid < 128) W2s[tid] = Wn2[tid];
    __syncthreads();

    int jb = warp * 8;
    ull acc[2][4];
    {
        ulonglong2 b01 = *(const ulonglong2*)(bn1 + jb);
        ulonglong2 b23 = *(const ulonglong2*)(bn1 + jb + 4);
        acc[0][0] = b01.x; acc[0][1] = b01.y; acc[0][2] = b23.x; acc[0][3] = b23.y;
#pragma unroll
        for (int i = 0; i < 4; i++) acc[1][i] = acc[0][i];
    }
#pragma unroll 8
    for (int k = 0; k < 128; k++) {
        const float* wr = W1s + k * 64 + jb;
        ulonglong2 wA = *(const ulonglong2*)(wr);
        ulonglong2 wB = *(const ulonglong2*)(wr + 4);
        float2 xv = *(const float2*)(Hst + k * 66 + lane * 2);
        ull x0 = pk2(xv.x, xv.x), x1 = pk2(xv.y, xv.y);
        ffma2(acc[0][0], x0, wA.x); ffma2(acc[0][1], x0, wA.y);
        ffma2(acc[0][2], x0, wB.x); ffma2(acc[0][3], x0, wB.y);
        ffma2(acc[1][0], x1, wA.x); ffma2(acc[1][1], x1, wA.y);
        ffma2(acc[1][2], x1, wB.x); ffma2(acc[1][3], x1, wB.y);
    }
#pragma unroll
    for (int rr = 0; rr < 2; rr++) {
        int r = lane * 2 + rr;
        float f[8];
#pragma unroll
        for (int i = 0; i < 4; i++) upk2(acc[rr][i], f[2 * i], f[2 * i + 1]);
        float4 o1, o2;
        o1.x = fmaxf(f[0], 0.f); o1.y = fmaxf(f[1], 0.f); o1.z = fmaxf(f[2], 0.f); o1.w = fmaxf(f[3], 0.f);
        o2.x = fmaxf(f[4], 0.f); o2.y = fmaxf(f[5], 0.f); o2.z = fmaxf(f[6], 0.f); o2.w = fmaxf(f[7], 0.f);
        *(float4*)(tsb + r * 68 + jb) = o1;
        *(float4*)(tsb + r * 68 + jb + 4) = o2;
    }
    __syncthreads();
    if (tid < 128) {
        int r = tid >> 1, o = tid & 1;
        float s = 0.f;
#pragma unroll 8
        for (int j = 0; j < 64; j++) s += tsb[r * 68 + j] * W2s[j * 2 + o];
        int gr = row0 + r;
        if (gr < NN) out[gr * 2 + o] = s + bn2[o];
    }
}

// ---------------- fused edge head ----------------
// t = relu(P[src]+Q[dst]+ea@We1c+be1); u = relu(t@We2+be2); out = u@We3+be3
#define EDGE_SMEM_FLOATS (8192 + 16896 + 8704 + 1024 + 384 + 128 + 64 + 8 + 1024)
__global__ void edge_kernel(const float* __restrict__ ea, const float* __restrict__ We1,
                            const float* __restrict__ be1, const float* __restrict__ We2,
                            const float* __restrict__ be2, const float* __restrict__ We3,
                            const float* __restrict__ be3, float* __restrict__ out) {
    extern __shared__ float esm[];
    float* w2s  = esm;            // [128 j][64 cols]
    float* ts   = w2s + 8192;     // [128 j][128 el] stride 132
    float* us   = ts + 16896;     // [128 el][64 j] stride 68
    float* wcs  = us + 8704;      // [8][128]
    float* w3t  = wcs + 1024;     // [6][64] transposed
    float* b1s  = w3t + 384;      // 128
    float* b2s  = b1s + 128;      // 64
    float* b3s  = b2s + 64;       // 8
    float* easm = b3s + 8;        // [128 el][8]
    __shared__ int esrc[128], edst[128];
    int tid = threadIdx.x, warp = tid >> 5, lane = tid & 31;

    for (int i = tid; i < 8192; i += 256) w2s[i] = We2[i];
    for (int i = tid; i < 1024; i += 256) wcs[i] = We1[256 * HD + i];
    for (int i = tid; i < 384; i += 256) w3t[i] = We3[(i & 63) * 6 + (i >> 6)];
    if (tid < 128) b1s[tid] = be1[tid];
    if (tid < 64) b2s[tid] = be2[tid];
    if (tid < 8) b3s[tid] = (tid < 6) ? be3[tid] : 0.f;
    __syncthreads();

    for (int e0 = blockIdx.x * 128; e0 < EE; e0 += gridDim.x * 128) {
        if (tid < 128) {
            int e = e0 + tid;
            esrc[tid] = (e < EE) ? g_src[e] : 0;
            edst[tid] = (e < EE) ? g_dst[e] : 0;
        }
        for (int i = tid; i < 1024; i += 256) {
            int el = i >> 3;
            int e = e0 + el;
            easm[i] = (e < EE) ? ea[e * EAD + (i & 7)] : 0.f;
        }
        __syncthreads();
        // phase 1: warp per edge, lane covers 4 j
        for (int el = warp; el < 128; el += 8) {
            int s = esrc[el], d = edst[el];
            int j0 = lane * 4;
            float4 t = *(const float4*)(b1s + j0);
#pragma unroll
            for (int k = 0; k < 8; k++) {
                float ev = easm[el * 8 + k];
                float4 w = *(const float4*)(wcs + k * 128 + j0);
                t.x += ev * w.x; t.y += ev * w.y; t.z += ev * w.z; t.w += ev * w.w;
            }
            float4 pp = *(const float4*)(g_P + s * HD + j0);
            float4 qq = *(const float4*)(g_Q + d * HD + j0);
            t.x = fmaxf(t.x + pp.x + qq.x, 0.f);
            t.y = fmaxf(t.y + pp.y + qq.y, 0.f);
            t.z = fmaxf(t.z + pp.z + qq.z, 0.f);
            t.w = fmaxf(t.w + pp.w + qq.w, 0.f);
            ts[(j0 + 0) * 132 + el] = t.x;
            ts[(j0 + 1) * 132 + el] = t.y;
            ts[(j0 + 2) * 132 + el] = t.z;
            ts[(j0 + 3) * 132 + el] = t.w;
        }
        __syncthreads();
        // phase 2: u = relu(t@We2 + be2); warp -> 8 cols, lane -> 4 edges
        int jb = warp * 8;
        ull a2[4][4];
        {
            ulonglong2 b01 = *(const ulonglong2*)(b2s + jb);
            ulonglong2 b23 = *(const ulonglong2*)(b2s + jb + 4);
#pragma unroll
            for (int e = 0; e < 4; e++) {
                a2[e][0] = b01.x; a2[e][1] = b01.y; a2[e][2] = b23.x; a2[e][3] = b23.y;
            }
        }
#pragma unroll 8
        for (int j = 0; j < 128; j++) {
            float4 tv = *(const float4*)(ts + j * 132 + lane * 4);
            ulonglong2 wA = *(const ulonglong2*)(w2s + j * 64 + jb);
            ulonglong2 wB = *(const ulonglong2*)(w2s + j * 64 + jb + 4);
            ull t0 = pk2(tv.x, tv.x), t1 = pk2(tv.y, tv.y);
            ull t2 = pk2(tv.z, tv.z), t3 = pk2(tv.w, tv.w);
            ffma2(a2[0][0], t0, wA.x); ffma2(a2[0][1], t0, wA.y); ffma2(a2[0][2], t0, wB.x); ffma2(a2[0][3], t0, wB.y);
            ffma2(a2[1][0], t1, wA.x); ffma2(a2[1][1], t1, wA.y); ffma2(a2[1][2], t1, wB.x); ffma2(a2[1][3], t1, wB.y);
            ffma2(a2[2][0], t2, wA.x); ffma2(a2[2][1], t2, wA.y); ffma2(a2[2][2], t2, wB.x); ffma2(a2[2][3], t2, wB.y);
            ffma2(a2[3][0], t3, wA.x); ffma2(a2[3][1], t3, wA.y); ffma2(a2[3][2], t3, wB.x); ffma2(a2[3][3], t3, wB.y);
        }
#pragma unroll
        for (int e = 0; e < 4; e++) {
            float f[8];
#pragma unroll
            for (int i = 0; i < 4; i++) upk2(a2[e][i], f[2 * i], f[2 * i + 1]);
            int el = lane * 4 + e;
            float4 o1, o2;
            o1.x = fmaxf(f[0], 0.f); o1.y = fmaxf(f[1], 0.f); o1.z = fmaxf(f[2], 0.f); o1.w = fmaxf(f[3], 0.f);
            o2.x = fmaxf(f[4], 0.f); o2.y = fmaxf(f[5], 0.f); o2.z = fmaxf(f[6], 0.f); o2.w = fmaxf(f[7], 0.f);
            *(float4*)(us + el * 68 + jb) = o1;
            *(float4*)(us + el * 68 + jb + 4) = o2;
        }
        __syncthreads();
        // phase 3: out = u@We3 + be3
        if (tid < 128) {
            int el = tid;
            int e = e0 + el;
            float av[6];
#pragma unroll
            for (int o = 0; o < 6; o++) av[o] = b3s[o];
#pragma unroll
            for (int q = 0; q < 16; q++) {
                float4 u = *(const float4*)(us + el * 68 + 4 * q);
#pragma unroll
                for (int o = 0; o < 6; o++) {
                    float4 w = *(const float4*)(w3t + o * 64 + 4 * q);
                    av[o] += u.x * w.x + u.y * w.y + u.z * w.z + u.w * w.w;
                }
            }
            if (e < EE) {
#pragma unroll
                for (int o = 0; o < 6; o++) out[e * 6 + o] = av[o];
            }
        }
        __syncthreads();
    }
}

// ---------------- launch ----------------
extern "C" void kernel_launch(void* const* d_in, const int* in_sizes, int n_in,
                              void* d_out, int out_size) {
    const float* x    = (const float*)d_in[0];
    const void*  ei   = d_in[1];
    const float* ea   = (const float*)d_in[2];
    const int*   lnum = (const int*)d_in[3];
    const float* Wenc = (const float*)d_in[4];
    const float* benc = (const float*)d_in[5];
    const float* Wmsg = (const float*)d_in[6];
    const float* bmsg = (const float*)d_in[7];
    const float* Wupd = (const float*)d_in[8];
    const float* bupd = (const float*)d_in[9];
    const float* Wn1  = (const float*)d_in[10];
    const float* bn1  = (const float*)d_in[11];
    const float* Wn2  = (const float*)d_in[12];
    const float* bn2  = (const float*)d_in[13];
    const float* We1  = (const float*)d_in[14];
    const float* be1  = (const float*)d_in[15];
    const float* We2  = (const float*)d_in[16];
    const float* be2  = (const float*)d_in[17];
    const float* We3  = (const float*)d_in[18];
    const float* be3  = (const float*)d_in[19];
    float* out = (float*)d_out;

    float *hp, *h2p;
    cudaGetSymbolAddress((void**)&hp,  g_h);
    cudaGetSymbolAddress((void**)&h2p, g_h2);

    const int layerSmem = LAYER_SMEM_FLOATS * 4;
    const int nhSmem    = NH_SMEM_FLOATS * 4;
    const int edgeSmem  = EDGE_SMEM_FLOATS * 4;
    cudaFuncSetAttribute(layer_kernel, cudaFuncAttributeMaxDynamicSharedMemorySize, layerSmem);
    cudaFuncSetAttribute(nodehead_kernel, cudaFuncAttributeMaxDynamicSharedMemorySize, nhSmem);
    cudaFuncSetAttribute(edge_kernel, cudaFuncAttributeMaxDynamicSharedMemorySize, edgeSmem);

    detect_kernel<<<256, 256>>>((const long long*)ei);
    prep_kernel<<<1024, 256>>>(ei);
    scan1_kernel<<<SCAN_NB, SCAN_B>>>();
    scan2_kernel<<<1, 128>>>();
    scan3_kernel<<<SCAN_NB, SCAN_B>>>();
    scatter_kernel<<<1024, 256>>>();
    uv_kernel<<<128, 128>>>(Wmsg, bmsg, Wupd, bupd);
    encoder_kernel<<<1184, 128>>>(x, Wenc, benc);

    const int grid64 = (NN + 63) / 64;  // 782
    for (int L = 0; L < MAX_LAYERS; L++) {
        const float* cur = (L & 1) ? h2p : hp;
        float* nxt = (L & 1) ? hp : h2p;
        layer_kernel<<<grid64, 256, layerSmem>>>(cur, nxt, lnum, L);
        fixup_kernel<<<32, 128>>>(Wupd, bupd, lnum, L, cur, nxt);
    }

    nodehead_kernel<<<grid64, 256, nhSmem>>>(Wn1, bn1, Wn2, bn2, out, lnum);
    pq_kernel<<<grid64, 256>>>(We1, lnum);
    edge_kernel<<<148, 256, edgeSmem>>>(ea, We1, be1, We2, be2, We3, be3, out + NODE_OUT_ELEMS);
}

// round 5
// speedup vs baseline: 2.4882x; 1.2891x over previous
#include <cuda_runtime.h>
#include <cuda_bf16.h>

// Problem constants (fixed by setup_inputs)
#define NN 50000
#define EE 400000
#define HD 128
#define FIN 16
#define EAD 8
#define MAX_LAYERS 6
#define NODE_OUT_ELEMS (NN * 2)
#define G64 ((NN + 63) / 64)   // 782

typedef unsigned long long ull;

// ---------------- scratch (device globals; no allocation allowed) ----------------
__device__ float g_h[NN * HD];
__device__ float g_h2[NN * HD];
__device__ float g_P[NN * HD];
__device__ float g_Q[NN * HD];
__device__ float g_U[HD * HD];
__device__ float g_V[HD * HD];
__device__ float g_c1[HD];

__device__ int g_src[EE];
__device__ int g_dst[EE];
__device__ int g_csrc[EE];
__device__ int g_deg[NN];
__device__ int g_rowptr[NN + 1];
__device__ int g_cursor[NN];
__device__ int g_zlist[NN];
__device__ int g_zcount;
__device__ int g_is64;
__device__ int g_bsum[128];

// ---------------- f32x2 helpers ----------------
__device__ __forceinline__ ull pk2(float lo, float hi) {
    ull r;
    asm("mov.b64 %0, {%1, %2};" : "=l"(r) : "f"(lo), "f"(hi));
    return r;
}
__device__ __forceinline__ void upk2(ull v, float& lo, float& hi) {
    asm("mov.b64 {%0, %1}, %2;" : "=f"(lo), "=f"(hi) : "l"(v));
}
__device__ __forceinline__ void ffma2(ull& d, ull a, ull b) {
    asm("fma.rn.f32x2 %0, %1, %2, %0;" : "+l"(d) : "l"(a), "l"(b));
}

// ---------------- detect dtype + zero deg ----------------
__global__ void detect_kernel(const long long* ei) {
    int idx = blockIdx.x * blockDim.x + threadIdx.x;
    int stride = gridDim.x * blockDim.x;
    for (int i = idx; i < NN; i += stride) g_deg[i] = 0;
    if (idx == 0) g_zcount = 0;
    if (blockIdx.x == 0) {
        __shared__ int bad;
        if (threadIdx.x == 0) bad = 0;
        __syncthreads();
        for (int i = threadIdx.x; i < 1024; i += blockDim.x) {
            long long v = ei[i];
            if (v < 0 || v >= NN) bad = 1;
        }
        __syncthreads();
        if (threadIdx.x == 0) g_is64 = bad ? 0 : 1;
    }
}

// ---------------- prep: convert + histogram ----------------
__global__ void prep_kernel(const void* ei) {
    int idx = blockIdx.x * blockDim.x + threadIdx.x;
    int stride = gridDim.x * blockDim.x;
    int is64 = g_is64;
    const long long* p64 = (const long long*)ei;
    const int* p32 = (const int*)ei;
    for (int i = idx; i < EE; i += stride) {
        int s, d;
        if (is64) {
            s = (int)p64[i];
            d = (int)p64[EE + i];
        } else {
            s = p32[i];
            d = p32[EE + i];
        }
        g_src[i] = s;
        g_dst[i] = d;
        atomicAdd(&g_deg[d], 1);
    }
}

// ---------------- multi-block exclusive scan ----------------
#define SCAN_B 512
#define SCAN_NB ((NN + SCAN_B - 1) / SCAN_B)   // 98

__global__ void scan1_kernel() {
    __shared__ int wsum[16];
    int b = blockIdx.x, tid = threadIdx.x;
    int i = b * SCAN_B + tid;
    int v = (i < NN) ? g_deg[i] : 0;
    int lane = tid & 31, w = tid >> 5;
    int x = v;
#pragma unroll
    for (int off = 1; off < 32; off <<= 1) {
        int t = __shfl_up_sync(0xffffffffu, x, off);
        if (lane >= off) x += t;
    }
    if (lane == 31) wsum[w] = x;
    __syncthreads();
    if (w == 0) {
        int s = (lane < 16) ? wsum[lane] : 0;
#pragma unroll
        for (int off = 1; off < 16; off <<= 1) {
            int t = __shfl_up_sync(0xffffffffu, s, off);
            if (lane >= off) s += t;
        }
        if (lane < 16) wsum[lane] = s;
    }
    __syncthreads();
    int base = (w > 0) ? wsum[w - 1] : 0;
    int incl = base + x;
    if (i < NN) g_rowptr[i] = incl - v;
    if (tid == SCAN_B - 1) g_bsum[b] = incl;
}

// scan3: adds block offset (computed inline from g_bsum) + nodeprep
__global__ void scan3_kernel() {
    __shared__ int boffs;
    int b = blockIdx.x, tid = threadIdx.x;
    if (tid < 32) {
        int s = 0;
        for (int i = tid; i < b; i += 32) s += g_bsum[i];
#pragma unroll
        for (int off = 16; off >= 1; off >>= 1) s += __shfl_xor_sync(0xffffffffu, s, off);
        if (tid == 0) boffs = s;
    }
    __syncthreads();
    int i = b * SCAN_B + tid;
    if (i < NN) {
        int rp = g_rowptr[i] + boffs;
        g_rowptr[i] = rp;
        g_cursor[i] = rp;
        if (g_deg[i] == 0) {
            int p = atomicAdd(&g_zcount, 1);
            g_zlist[p] = i;
        }
    }
    if (b == 0 && tid == 0) g_rowptr[NN] = EE;
}

__global__ void scatter_kernel() {
    int idx = blockIdx.x * blockDim.x + threadIdx.x;
    int stride = gridDim.x * blockDim.x;
    for (int i = idx; i < EE; i += stride) {
        int d = g_dst[i];
        int pos = atomicAdd(&g_cursor[d], 1);
        g_csrc[pos] = g_src[i];
    }
}

// ---------------- encoder + uv fused ----------------
__global__ void encuv_kernel(const float* __restrict__ x, const float* __restrict__ Wenc,
                             const float* __restrict__ benc,
                             const float* __restrict__ Wmsg, const float* __restrict__ bmsg,
                             const float* __restrict__ Wupd, const float* __restrict__ bupd) {
    if (blockIdx.x >= 1184) {
        // uv path: U = Wu_a + Wb@Wu_b, V = Wt@Wu_b
        int k = blockIdx.x - 1184;   // 0..127
        int j = threadIdx.x;         // 0..127
        float u = Wupd[k * HD + j];
        float v = 0.f;
        for (int t = 0; t < HD; t++) {
            float wub = Wupd[(HD + t) * HD + j];
            u += Wmsg[(HD + k) * HD + t] * wub;
            v += Wmsg[k * HD + t] * wub;
        }
        g_U[k * HD + j] = u;
        g_V[k * HD + j] = v;
        if (k == 0) {
            float c = bupd[j];
            for (int t = 0; t < HD; t++) c += bmsg[t] * Wupd[(HD + t) * HD + j];
            g_c1[j] = c;
        }
        return;
    }
    __shared__ float ws[FIN * HD];
    __shared__ float bs[HD];
    __shared__ float xs[FIN];
    int tid = threadIdx.x;  // 128
    for (int i = tid; i < FIN * HD; i += 128) ws[i] = Wenc[i];
    bs[tid] = benc[tid];
    __syncthreads();
    for (int v = blockIdx.x; v < NN; v += 1184) {
        if (tid < FIN) xs[tid] = x[v * FIN + tid];
        __syncthreads();
        float acc = bs[tid];
#pragma unroll
        for (int k = 0; k < FIN; k++) acc += xs[k] * ws[k * HD + tid];
        g_h[v * HD + tid] = acc;
        __syncthreads();
    }
}

// ---------------- fused layer: agg + h' = relu(h@U + A@V + c1) + zero-deg fixup ----------
#define LAYER_SMEM_FLOATS (8448 + 8448 + 1024)
__global__ void __launch_bounds__(256, 3)
layer_kernel(const float* __restrict__ hcur, float* __restrict__ hnext,
             const int* __restrict__ lnum, int layer,
             const float* __restrict__ Wupd, const float* __restrict__ bupd) {
    if (layer >= *lnum) return;
    int tid = threadIdx.x;
    if (blockIdx.x >= G64) {
        // fixup blocks: hnext[v] = relu(hcur[v]@Wu_a + b_upd) for zero-in-degree v
        __shared__ float hs[HD];
        int zc = g_zcount;
        for (int zi = blockIdx.x - G64; zi < zc; zi += 32) {
            int v = g_zlist[zi];
            if (tid < 128) hs[tid] = hcur[v * HD + tid];
            __syncthreads();
            if (tid < 128) {
                float acc = bupd[tid];
#pragma unroll 8
                for (int k = 0; k < HD; k++) acc += hs[k] * Wupd[k * HD + tid];
                hnext[v * HD + tid] = fmaxf(acc, 0.f);
            }
            __syncthreads();
        }
        return;
    }
    extern __shared__ float lsm[];
    float* Hst = lsm;            // [k 128][r 64] stride 66
    float* Ast = Hst + 8448;     // [k 128][r 64] stride 66
    float* Ws  = Ast + 8448;     // [8][128] chunk
    int warp = tid >> 5, lane = tid & 31;
    int row0 = blockIdx.x * 64;

    // stage Hst transposed (coalesced reads)
#pragma unroll 4
    for (int q = 0; q < 32; q++) {
        int e = tid + 256 * q;
        int r = e >> 7, k = e & 127;
        int gr = row0 + r;
        Hst[k * 66 + r] = (gr < NN) ? hcur[gr * HD + k] : 0.f;
    }

    // mean-aggregate into Ast (transposed); warp per node, MLP-4 gather
    for (int n = warp; n < 64; n += 8) {
        int v = row0 + n;
        float4 a0 = make_float4(0.f, 0.f, 0.f, 0.f);
        float4 a1 = make_float4(0.f, 0.f, 0.f, 0.f);
        float4 a2 = make_float4(0.f, 0.f, 0.f, 0.f);
        float4 a3 = make_float4(0.f, 0.f, 0.f, 0.f);
        int dg = 0;
        if (v < NN) {
            int s0r = g_rowptr[v], s1r = g_rowptr[v + 1];
            dg = s1r - s0r;
            int idx = s0r;
            for (; idx + 3 < s1r; idx += 4) {
                int i0 = g_csrc[idx], i1 = g_csrc[idx + 1];
                int i2 = g_csrc[idx + 2], i3 = g_csrc[idx + 3];
                float4 h0 = __ldg((const float4*)(hcur + i0 * HD + lane * 4));
                float4 h1 = __ldg((const float4*)(hcur + i1 * HD + lane * 4));
                float4 h2 = __ldg((const float4*)(hcur + i2 * HD + lane * 4));
                float4 h3 = __ldg((const float4*)(hcur + i3 * HD + lane * 4));
                a0.x += h0.x; a0.y += h0.y; a0.z += h0.z; a0.w += h0.w;
                a1.x += h1.x; a1.y += h1.y; a1.z += h1.z; a1.w += h1.w;
                a2.x += h2.x; a2.y += h2.y; a2.z += h2.z; a2.w += h2.w;
                a3.x += h3.x; a3.y += h3.y; a3.z += h3.z; a3.w += h3.w;
            }
            for (; idx < s1r; idx++) {
                int i0 = g_csrc[idx];
                float4 h0 = __ldg((const float4*)(hcur + i0 * HD + lane * 4));
                a0.x += h0.x; a0.y += h0.y; a0.z += h0.z; a0.w += h0.w;
            }
        }
        float inv = 1.f / (float)(dg > 0 ? dg : 1);
        int j0 = lane * 4;
        Ast[(j0 + 0) * 66 + n] = (a0.x + a1.x + a2.x + a3.x) * inv;
        Ast[(j0 + 1) * 66 + n] = (a0.y + a1.y + a2.y + a3.y) * inv;
        Ast[(j0 + 2) * 66 + n] = (a0.z + a1.z + a2.z + a3.z) * inv;
        Ast[(j0 + 3) * 66 + n] = (a0.w + a1.w + a2.w + a3.w) * inv;
    }
    __syncthreads();

    int jb = warp * 16;
    ull acc[2][8];
    {
        const ulonglong2* cp = (const ulonglong2*)(g_c1 + jb);
        ulonglong2 q0 = cp[0], q1 = cp[1], q2 = cp[2], q3 = cp[3];
        acc[0][0] = q0.x; acc[0][1] = q0.y; acc[0][2] = q1.x; acc[0][3] = q1.y;
        acc[0][4] = q2.x; acc[0][5] = q2.y; acc[0][6] = q3.x; acc[0][7] = q3.y;
#pragma unroll
        for (int i = 0; i < 8; i++) acc[1][i] = acc[0][i];
    }
    for (int pass = 0; pass < 2; pass++) {
        const float* Wg = pass ? g_V : g_U;
        const float* Xt = pass ? Ast : Hst;
        for (int c = 0; c < 16; c++) {
#pragma unroll
            for (int q = 0; q < 4; q++) Ws[tid + 256 * q] = Wg[c * 1024 + tid + 256 * q];
            __syncthreads();
#pragma unroll
            for (int kk = 0; kk < 8; kk++) {
                const float* wr = Ws + kk * 128 + jb;
                ulonglong2 wA = *(const ulonglong2*)(wr);
                ulonglong2 wB = *(const ulonglong2*)(wr + 4);
                ulonglong2 wC = *(const ulonglong2*)(wr + 8);
                ulonglong2 wD = *(const ulonglong2*)(wr + 12);
                float2 xv = *(const float2*)(Xt + (c * 8 + kk) * 66 + lane * 2);
                ull x0 = pk2(xv.x, xv.x), x1 = pk2(xv.y, xv.y);
                ffma2(acc[0][0], x0, wA.x); ffma2(acc[0][1], x0, wA.y);
                ffma2(acc[0][2], x0, wB.x); ffma2(acc[0][3], x0, wB.y);
                ffma2(acc[0][4], x0, wC.x); ffma2(acc[0][5], x0, wC.y);
                ffma2(acc[0][6], x0, wD.x); ffma2(acc[0][7], x0, wD.y);
                ffma2(acc[1][0], x1, wA.x); ffma2(acc[1][1], x1, wA.y);
                ffma2(acc[1][2], x1, wB.x); ffma2(acc[1][3], x1, wB.y);
                ffma2(acc[1][4], x1, wC.x); ffma2(acc[1][5], x1, wC.y);
                ffma2(acc[1][6], x1, wD.x); ffma2(acc[1][7], x1, wD.y);
            }
            __syncthreads();
        }
    }
#pragma unroll
    for (int rr = 0; rr < 2; rr++) {
        int r = row0 + lane * 2 + rr;
        if (r < NN && g_deg[r] != 0) {
            float f[16];
#pragma unroll
            for (int i = 0; i < 8; i++) upk2(acc[rr][i], f[2 * i], f[2 * i + 1]);
            float4* dst = (float4*)(hnext + r * HD + jb);
#pragma unroll
            for (int qq = 0; qq < 4; qq++) {
                float4 o;
                o.x = fmaxf(f[4 * qq + 0], 0.f); o.y = fmaxf(f[4 * qq + 1], 0.f);
                o.z = fmaxf(f[4 * qq + 2], 0.f); o.w = fmaxf(f[4 * qq + 3], 0.f);
                dst[qq] = o;
            }
        }
    }
}

// ---------------- fused P/Q + node head ----------------
#define PQNH_SMEM_FLOATS (8448 + 2048 + 4352 + 128)
__global__ void pqnh_kernel(const float* __restrict__ We1,
                            const float* __restrict__ Wn1, const float* __restrict__ bn1,
                            const float* __restrict__ Wn2, const float* __restrict__ bn2,
                            float* __restrict__ out, const int* __restrict__ lnum) {
    const float* X = ((*lnum) & 1) ? g_h2 : g_h;
    extern __shared__ float psm[];
    float* Hst  = psm;            // [k 128][r 64] stride 66
    float* Wbuf = Hst + 8448;     // 2048 chunk
    float* tsb  = Wbuf + 2048;    // [r 64][j 64] stride 68
    float* W2s  = tsb + 4352;     // 64*2
    int tid = threadIdx.x;
    int warp = tid >> 5, lane = tid & 31;
    int row0 = blockIdx.x * 64;
    if (tid < 128) W2s[tid] = Wn2[tid];
#pragma unroll 4
    for (int q = 0; q < 32; q++) {
        int e = tid + 256 * q;
        int r = e >> 7, k = e & 127;
        int gr = row0 + r;
        Hst[k * 66 + r] = (gr < NN) ? X[gr * HD + k] : 0.f;
    }
    __syncthreads();

    // ---- P/Q GEMMs ----
    int jb = warp * 16;
    for (int m = 0; m < 2; m++) {
        const float* Wg = We1 + m * 128 * HD;
        float* C = m ? g_Q : g_P;
        ull acc[2][8];
        ull z = pk2(0.f, 0.f);
#pragma unroll
        for (int i = 0; i < 8; i++) { acc[0][i] = z; acc[1][i] = z; }
        for (int c = 0; c < 8; c++) {
#pragma unroll
            for (int q = 0; q < 8; q++) Wbuf[tid + 256 * q] = Wg[c * 2048 + tid + 256 * q];
            __syncthreads();
#pragma unroll
            for (int kk = 0; kk < 16; kk++) {
                const float* wr = Wbuf + kk * 128 + jb;
                ulonglong2 wA = *(const ulonglong2*)(wr);
                ulonglong2 wB = *(const ulonglong2*)(wr + 4);
                ulonglong2 wC = *(const ulonglong2*)(wr + 8);
                ulonglong2 wD = *(const ulonglong2*)(wr + 12);
                float2 xv = *(const float2*)(Hst + (c * 16 + kk) * 66 + lane * 2);
                ull x0 = pk2(xv.x, xv.x), x1 = pk2(xv.y, xv.y);
                ffma2(acc[0][0], x0, wA.x); ffma2(acc[0][1], x0, wA.y);
                ffma2(acc[0][2], x0, wB.x); ffma2(acc[0][3], x0, wB.y);
                ffma2(acc[0][4], x0, wC.x); ffma2(acc[0][5], x0, wC.y);
                ffma2(acc[0][6], x0, wD.x); ffma2(acc[0][7], x0, wD.y);
                ffma2(acc[1][0], x1, wA.x); ffma2(acc[1][1], x1, wA.y);
                ffma2(acc[1][2], x1, wB.x); ffma2(acc[1][3], x1, wB.y);
                ffma2(acc[1][4], x1, wC.x); ffma2(acc[1][5], x1, wC.y);
                ffma2(acc[1][6], x1, wD.x); ffma2(acc[1][7], x1, wD.y);
            }
            __syncthreads();
        }
#pragma unroll
        for (int rr = 0; rr < 2; rr++) {
            int r = row0 + lane * 2 + rr;
            if (r < NN) {
                float f[16];
#pragma unroll
                for (int i = 0; i < 8; i++) upk2(acc[rr][i], f[2 * i], f[2 * i + 1]);
                float4* dst = (float4*)(C + r * HD + jb);
#pragma unroll
                for (int qq = 0; qq < 4; qq++) {
                    float4 o;
                    o.x = f[4 * qq + 0]; o.y = f[4 * qq + 1];
                    o.z = f[4 * qq + 2]; o.w = f[4 * qq + 3];
                    dst[qq] = o;
                }
            }
        }
    }

    // ---- node head stage 1 (chunked W1) ----
    int jb8 = warp * 8;
    ull acc2[2][4];
    {
        ulonglong2 b01 = *(const ulonglong2*)(bn1 + jb8);
        ulonglong2 b23 = *(const ulonglong2*)(bn1 + jb8 + 4);
        acc2[0][0] = b01.x; acc2[0][1] = b01.y; acc2[0][2] = b23.x; acc2[0][3] = b23.y;
#pragma unroll
        for (int i = 0; i < 4; i++) acc2[1][i] = acc2[0][i];
    }
    for (int c = 0; c < 4; c++) {
#pragma unroll
        for (int q = 0; q < 8; q++) Wbuf[tid + 256 * q] = Wn1[c * 2048 + tid + 256 * q];
        __syncthreads();
#pragma unroll 8
        for (int kk = 0; kk < 32; kk++) {
            const float* wr = Wbuf + kk * 64 + jb8;
            ulonglong2 wA = *(const ulonglong2*)(wr);
            ulonglong2 wB = *(const ulonglong2*)(wr + 4);
            float2 xv = *(const float2*)(Hst + (c * 32 + kk) * 66 + lane * 2);
            ull x0 = pk2(xv.x, xv.x), x1 = pk2(xv.y, xv.y);
            ffma2(acc2[0][0], x0, wA.x); ffma2(acc2[0][1], x0, wA.y);
            ffma2(acc2[0][2], x0, wB.x); ffma2(acc2[0][3], x0, wB.y);
            ffma2(acc2[1][0], x1, wA.x); ffma2(acc2[1][1], x1, wA.y);
            ffma2(acc2[1][2], x1, wB.x); ffma2(acc2[1][3], x1, wB.y);
        }
        __syncthreads();
    }
#pragma unroll
    for (int rr = 0; rr < 2; rr++) {
        int r = lane * 2 + rr;
        float f[8];
#pragma unroll
        for (int i = 0; i < 4; i++) upk2(acc2[rr][i], f[2 * i], f[2 * i + 1]);
        float4 o1, o2;
        o1.x = fmaxf(f[0], 0.f); o1.y = fmaxf(f[1], 0.f); o1.z = fmaxf(f[2], 0.f); o1.w = fmaxf(f[3], 0.f);
        o2.x = fmaxf(f[4], 0.f); o2.y = fmaxf(f[5], 0.f); o2.z = fmaxf(f[6], 0.f); o2.w = fmaxf(f[7], 0.f);
        *(float4*)(tsb + r * 68 + jb8) = o1;
        *(float4*)(tsb + r * 68 + jb8 + 4) = o2;
    }
    __syncthreads();
    if (tid < 128) {
        int r = tid >> 1, o = tid & 1;
        float s = 0.f;
#pragma unroll 8
        for (int j = 0; j < 64; j++) s += tsb[r * 68 + j] * W2s[j * 2 + o];
        int gr = row0 + r;
        if (gr < NN) out[gr * 2 + o] = s + bn2[o];
    }
}

// ---------------- fused edge head ----------------
// t = relu(P[src]+Q[dst]+ea@We1c+be1); u = relu(t@We2+be2); out = u@We3+be3
// ts el-major (conflict-free STS.128); phase2 spread-el reads; W2 via __ldg (L1).
#define EDGE_SMEM_FLOATS (16896 + 8704 + 384 + 8)
#define P2STEP(CMP, JJ)                                                              \
    {                                                                                \
        const ulonglong2* wp = (const ulonglong2*)(wbase + (JJ) * 64);               \
        ulonglong2 wA = __ldg(wp);                                                   \
        ulonglong2 wB = __ldg(wp + 1);                                               \
        ull x0 = pk2(t0.CMP, t0.CMP), x1 = pk2(t1.CMP, t1.CMP);                      \
        ull x2 = pk2(t2.CMP, t2.CMP), x3 = pk2(t3.CMP, t3.CMP);                      \
        ffma2(acc[0][0], x0, wA.x); ffma2(acc[0][1], x0, wA.y);                      \
        ffma2(acc[0][2], x0, wB.x); ffma2(acc[0][3], x0, wB.y);                      \
        ffma2(acc[1][0], x1, wA.x); ffma2(acc[1][1], x1, wA.y);                      \
        ffma2(acc[1][2], x1, wB.x); ffma2(acc[1][3], x1, wB.y);                      \
        ffma2(acc[2][0], x2, wA.x); ffma2(acc[2][1], x2, wA.y);                      \
        ffma2(acc[2][2], x2, wB.x); ffma2(acc[2][3], x2, wB.y);                      \
        ffma2(acc[3][0], x3, wA.x); ffma2(acc[3][1], x3, wA.y);                      \
        ffma2(acc[3][2], x3, wB.x); ffma2(acc[3][3], x3, wB.y);                      \
    }
__global__ void __launch_bounds__(256, 2)
edge_kernel(const float* __restrict__ ea, const float* __restrict__ We1,
            const float* __restrict__ be1, const float* __restrict__ We2,
            const float* __restrict__ be2, const float* __restrict__ We3,
            const float* __restrict__ be3, float* __restrict__ out) {
    extern __shared__ float esm[];
    float* ts  = esm;             // [128 el][132 j]
    float* us  = ts + 16896;      // [128 el][68 j]
    float* w3t = us + 8704;       // [6][64] transposed
    float* b3s = w3t + 384;       // 8
    __shared__ int esrc[128], edst[128];
    int tid = threadIdx.x, warp = tid >> 5, lane = tid & 31;
    int j0 = lane * 4;

    for (int i = tid; i < 384; i += 256) w3t[i] = We3[(i & 63) * 6 + (i >> 6)];
    if (tid < 8) b3s[tid] = (tid < 6) ? be3[tid] : 0.f;

    // hoisted phase-1 constants (reused across all tiles)
    float4 bq = __ldg((const float4*)(be1 + j0));
    float4 wck[8];
#pragma unroll
    for (int k = 0; k < 8; k++)
        wck[k] = __ldg((const float4*)(We1 + 256 * HD + k * 128 + j0));
    // hoisted phase-2 bias (per warp)
    int jb = warp * 8;
    ulonglong2 b2a = __ldg((const ulonglong2*)(be2 + jb));
    ulonglong2 b2b = __ldg((const ulonglong2*)(be2 + jb + 4));
    __syncthreads();

    for (int e0 = blockIdx.x * 128; e0 < EE; e0 += gridDim.x * 128) {
        if (tid < 128) {
            int e = e0 + tid;
            esrc[tid] = g_src[e];
            edst[tid] = g_dst[e];
        }
        __syncthreads();
        // ---- phase 1: warp per edge; 2-edge prefetch; conflict-free el-major STS ----
        for (int it = 0; it < 8; it++) {
            int elA = warp + 8 * (2 * it);
            int elB = elA + 8;
            int sA = esrc[elA], dA = edst[elA];
            int sB = esrc[elB], dB = edst[elB];
            float4 pA = __ldg((const float4*)(g_P + sA * HD + j0));
            float4 qA = __ldg((const float4*)(g_Q + dA * HD + j0));
            float4 pB = __ldg((const float4*)(g_P + sB * HD + j0));
            float4 qB = __ldg((const float4*)(g_Q + dB * HD + j0));
            float4 eA0 = __ldg((const float4*)(ea + (e0 + elA) * EAD));
            float4 eA1 = __ldg((const float4*)(ea + (e0 + elA) * EAD + 4));
            float4 eB0 = __ldg((const float4*)(ea + (e0 + elB) * EAD));
            float4 eB1 = __ldg((const float4*)(ea + (e0 + elB) * EAD + 4));
            float4 t = bq;
            t.x += eA0.x * wck[0].x + eA0.y * wck[1].x + eA0.z * wck[2].x + eA0.w * wck[3].x
                 + eA1.x * wck[4].x + eA1.y * wck[5].x + eA1.z * wck[6].x + eA1.w * wck[7].x;
            t.y += eA0.x * wck[0].y + eA0.y * wck[1].y + eA0.z * wck[2].y + eA0.w * wck[3].y
                 + eA1.x * wck[4].y + eA1.y * wck[5].y + eA1.z * wck[6].y + eA1.w * wck[7].y;
            t.z += eA0.x * wck[0].z + eA0.y * wck[1].z + eA0.z * wck[2].z + eA0.w * wck[3].z
                 + eA1.x * wck[4].z + eA1.y * wck[5].z + eA1.z * wck[6].z + eA1.w * wck[7].z;
            t.w += eA0.x * wck[0].w + eA0.y * wck[1].w + eA0.z * wck[2].w + eA0.w * wck[3].w
                 + eA1.x * wck[4].w + eA1.y * wck[5].w + eA1.z * wck[6].w + eA1.w * wck[7].w;
            t.x = fmaxf(t.x + pA.x + qA.x, 0.f);
            t.y = fmaxf(t.y + pA.y + qA.y, 0.f);
            t.z = fmaxf(t.z + pA.z + qA.z, 0.f);
            t.w = fmaxf(t.w + pA.w + qA.w, 0.f);
            *(float4*)(ts + elA * 132 + j0) = t;
            float4 u = bq;
            u.x += eB0.x * wck[0].x + eB0.y * wck[1].x + eB0.z * wck[2].x + eB0.w * wck[3].x
                 + eB1.x * wck[4].x + eB1.y * wck[5].x + eB1.z * wck[6].x + eB1.w * wck[7].x;
            u.y += eB0.x * wck[0].y + eB0.y * wck[1].y + eB0.z * wck[2].y + eB0.w * wck[3].y
                 + eB1.x * wck[4].y + eB1.y * wck[5].y + eB1.z * wck[6].y + eB1.w * wck[7].y;
            u.z += eB0.x * wck[0].z + eB0.y * wck[1].z + eB0.z * wck[2].z + eB0.w * wck[3].z
                 + eB1.x * wck[4].z + eB1.y * wck[5].z + eB1.z * wck[6].z + eB1.w * wck[7].z;
            u.w += eB0.x * wck[0].w + eB0.y * wck[1].w + eB0.z * wck[2].w + eB0.w * wck[3].w
                 + eB1.x * wck[4].w + eB1.y * wck[5].w + eB1.z * wck[6].w + eB1.w * wck[7].w;
            u.x = fmaxf(u.x + pB.x + qB.x, 0.f);
            u.y = fmaxf(u.y + pB.y + qB.y, 0.f);
            u.z = fmaxf(u.z + pB.z + qB.z, 0.f);
            u.w = fmaxf(u.w + pB.w + qB.w, 0.f);
            *(float4*)(ts + elB * 132 + j0) = u;
        }
        __syncthreads();
        // ---- phase 2: warp -> 8 cols, lane -> 4 spread edges; W2 via __ldg ----
        ull acc[4][4];
#pragma unroll
        for (int e = 0; e < 4; e++) {
            acc[e][0] = b2a.x; acc[e][1] = b2a.y; acc[e][2] = b2b.x; acc[e][3] = b2b.y;
        }
#pragma unroll 2
        for (int jv = 0; jv < 128; jv += 4) {
            float4 t0 = *(const float4*)(ts + (lane) * 132 + jv);
            float4 t1 = *(const float4*)(ts + (lane + 32) * 132 + jv);
            float4 t2 = *(const float4*)(ts + (lane + 64) * 132 + jv);
            float4 t3 = *(const float4*)(ts + (lane + 96) * 132 + jv);
            const float* wbase = We2 + jv * 64 + jb;
            P2STEP(x, 0)
            P2STEP(y, 1)
            P2STEP(z, 2)
            P2STEP(w, 3)
        }
#pragma unroll
        for (int e = 0; e < 4; e++) {
            int el = lane + 32 * e;
            float f[8];
#pragma unroll
            for (int i = 0; i < 4; i++) upk2(acc[e][i], f[2 * i], f[2 * i + 1]);
            float4 o1, o2;
            o1.x = fmaxf(f[0], 0.f); o1.y = fmaxf(f[1], 0.f); o1.z = fmaxf(f[2], 0.f); o1.w = fmaxf(f[3], 0.f);
            o2.x = fmaxf(f[4], 0.f); o2.y = fmaxf(f[5], 0.f); o2.z = fmaxf(f[6], 0.f); o2.w = fmaxf(f[7], 0.f);
            *(float4*)(us + el * 68 + jb) = o1;
            *(float4*)(us + el * 68 + jb + 4) = o2;
        }
        __syncthreads();
        // ---- phase 3: out = u@We3 + be3; thread -> (edge, 3 outputs) ----
        {
            int el = tid >> 1;
            int o3 = (tid & 1) * 3;
            float a0 = b3s[o3], a1 = b3s[o3 + 1], a2 = b3s[o3 + 2];
#pragma unroll
            for (int q = 0; q < 16; q++) {
                float4 u = *(const float4*)(us + el * 68 + 4 * q);
                float4 w0 = *(const float4*)(w3t + (o3 + 0) * 64 + 4 * q);
                float4 w1 = *(const float4*)(w3t + (o3 + 1) * 64 + 4 * q);
                float4 w2 = *(const float4*)(w3t + (o3 + 2) * 64 + 4 * q);
                a0 += u.x * w0.x + u.y * w0.y + u.z * w0.z + u.w * w0.w;
                a1 += u.x * w1.x + u.y * w1.y + u.z * w1.z + u.w * w1.w;
                a2 += u.x * w2.x + u.y * w2.y + u.z * w2.z + u.w * w2.w;
            }
            int e = e0 + el;
            out[e * 6 + o3 + 0] = a0;
            out[e * 6 + o3 + 1] = a1;
            out[e * 6 + o3 + 2] = a2;
        }
        __syncthreads();
    }
}

// ---------------- launch ----------------
extern "C" void kernel_launch(void* const* d_in, const int* in_sizes, int n_in,
                              void* d_out, int out_size) {
    const float* x    = (const float*)d_in[0];
    const void*  ei   = d_in[1];
    const float* ea   = (const float*)d_in[2];
    const int*   lnum = (const int*)d_in[3];
    const float* Wenc = (const float*)d_in[4];
    const float* benc = (const float*)d_in[5];
    const float* Wmsg = (const float*)d_in[6];
    const float* bmsg = (const float*)d_in[7];
    const float* Wupd = (const float*)d_in[8];
    const float* bupd = (const float*)d_in[9];
    const float* Wn1  = (const float*)d_in[10];
    const float* bn1  = (const float*)d_in[11];
    const float* Wn2  = (const float*)d_in[12];
    const float* bn2  = (const float*)d_in[13];
    const float* We1  = (const float*)d_in[14];
    const float* be1  = (const float*)d_in[15];
    const float* We2  = (const float*)d_in[16];
    const float* be2  = (const float*)d_in[17];
    const float* We3  = (const float*)d_in[18];
    const float* be3  = (const float*)d_in[19];
    float* out = (float*)d_out;

    float *hp, *h2p;
    cudaGetSymbolAddress((void**)&hp,  g_h);
    cudaGetSymbolAddress((void**)&h2p, g_h2);

    const int layerSmem = LAYER_SMEM_FLOATS * 4;
    const int pqnhSmem  = PQNH_SMEM_FLOATS * 4;
    const int edgeSmem  = EDGE_SMEM_FLOATS * 4;
    cudaFuncSetAttribute(layer_kernel, cudaFuncAttributeMaxDynamicSharedMemorySize, layerSmem);
    cudaFuncSetAttribute(pqnh_kernel, cudaFuncAttributeMaxDynamicSharedMemorySize, pqnhSmem);
    cudaFuncSetAttribute(edge_kernel, cudaFuncAttributeMaxDynamicSharedMemorySize, edgeSmem);

    detect_kernel<<<256, 256>>>((const long long*)ei);
    prep_kernel<<<1024, 256>>>(ei);
    scan1_kernel<<<SCAN_NB, SCAN_B>>>();
    scan3_kernel<<<SCAN_NB, SCAN_B>>>();
    scatter_kernel<<<1024, 256>>>();
    encuv_kernel<<<1312, 128>>>(x, Wenc, benc, Wmsg, bmsg, Wupd, bupd);

    for (int L = 0; L < MAX_LAYERS; L++) {
        const float* cur = (L & 1) ? h2p : hp;
        float* nxt = (L & 1) ? hp : h2p;
        layer_kernel<<<G64 + 32, 256, layerSmem>>>(cur, nxt, lnum, L, Wupd, bupd);
    }

    pqnh_kernel<<<G64, 256, pqnhSmem>>>(We1, Wn1, bn1, Wn2, bn2, out, lnum);
    edge_kernel<<<296, 256, edgeSmem>>>(ea, We1, be1, We2, be2, We3, be3, out + NODE_OUT_ELEMS);
}

// round 6
// speedup vs baseline: 2.5231x; 1.0140x over previous
#include <cuda_runtime.h>
#include <cuda_bf16.h>

// Problem constants (fixed by setup_inputs)
#define NN 50000
#define EE 400000
#define HD 128
#define FIN 16
#define EAD 8
#define MAX_LAYERS 6
#define NODE_OUT_ELEMS (NN * 2)
#define G64 ((NN + 63) / 64)   // 782
#define LGRID 391              // 2 tiles per block, 2*391 = 782

typedef unsigned long long ull;

// ---------------- scratch (device globals; no allocation allowed) ----------------
__device__ float g_h[NN * HD];
__device__ float g_h2[NN * HD];
__device__ float g_P[NN * HD];
__device__ float g_Q[NN * HD];
__device__ float g_U[HD * HD];
__device__ float g_V[HD * HD];
__device__ float g_c1[HD];

__device__ int g_src[EE];
__device__ int g_dst[EE];
__device__ int g_csrc[EE];
__device__ int g_deg[NN];
__device__ int g_rowptr[NN + 1];
__device__ int g_cursor[NN];
__device__ int g_zlist[NN];
__device__ int g_zcount;
__device__ int g_is64;
__device__ int g_bsum[128];

// ---------------- f32x2 helpers ----------------
__device__ __forceinline__ ull pk2(float lo, float hi) {
    ull r;
    asm("mov.b64 %0, {%1, %2};" : "=l"(r) : "f"(lo), "f"(hi));
    return r;
}
__device__ __forceinline__ void upk2(ull v, float& lo, float& hi) {
    asm("mov.b64 {%0, %1}, %2;" : "=f"(lo), "=f"(hi) : "l"(v));
}
__device__ __forceinline__ void ffma2(ull& d, ull a, ull b) {
    asm("fma.rn.f32x2 %0, %1, %2, %0;" : "+l"(d) : "l"(a), "l"(b));
}

// ---------------- streams/events for capture-forked concurrency ----------------
static cudaStream_t s_b = 0;
static cudaEvent_t s_ev0 = 0, s_ev1 = 0, s_evB = 0, s_evB2 = 0;
static bool s_fork = false;
static struct StreamInit {
    StreamInit() {
        bool ok = true;
        ok = ok && (cudaStreamCreateWithFlags(&s_b, cudaStreamNonBlocking) == cudaSuccess);
        ok = ok && (cudaEventCreateWithFlags(&s_ev0, cudaEventDisableTiming) == cudaSuccess);
        ok = ok && (cudaEventCreateWithFlags(&s_ev1, cudaEventDisableTiming) == cudaSuccess);
        ok = ok && (cudaEventCreateWithFlags(&s_evB, cudaEventDisableTiming) == cudaSuccess);
        ok = ok && (cudaEventCreateWithFlags(&s_evB2, cudaEventDisableTiming) == cudaSuccess);
        s_fork = ok;
    }
} s_streaminit;

// ---------------- detect dtype + zero deg ----------------
__global__ void detect_kernel(const long long* ei) {
    int idx = blockIdx.x * blockDim.x + threadIdx.x;
    int stride = gridDim.x * blockDim.x;
    for (int i = idx; i < NN; i += stride) g_deg[i] = 0;
    if (idx == 0) g_zcount = 0;
    if (blockIdx.x == 0) {
        __shared__ int bad;
        if (threadIdx.x == 0) bad = 0;
        __syncthreads();
        for (int i = threadIdx.x; i < 1024; i += blockDim.x) {
            long long v = ei[i];
            if (v < 0 || v >= NN) bad = 1;
        }
        __syncthreads();
        if (threadIdx.x == 0) g_is64 = bad ? 0 : 1;
    }
}

// ---------------- prep: convert + histogram ----------------
__global__ void prep_kernel(const void* ei) {
    int idx = blockIdx.x * blockDim.x + threadIdx.x;
    int stride = gridDim.x * blockDim.x;
    int is64 = g_is64;
    const long long* p64 = (const long long*)ei;
    const int* p32 = (const int*)ei;
    for (int i = idx; i < EE; i += stride) {
        int s, d;
        if (is64) {
            s = (int)p64[i];
            d = (int)p64[EE + i];
        } else {
            s = p32[i];
            d = p32[EE + i];
        }
        g_src[i] = s;
        g_dst[i] = d;
        atomicAdd(&g_deg[d], 1);
    }
}

// ---------------- multi-block exclusive scan ----------------
#define SCAN_B 512
#define SCAN_NB ((NN + SCAN_B - 1) / SCAN_B)   // 98

__global__ void scan1_kernel() {
    __shared__ int wsum[16];
    int b = blockIdx.x, tid = threadIdx.x;
    int i = b * SCAN_B + tid;
    int v = (i < NN) ? g_deg[i] : 0;
    int lane = tid & 31, w = tid >> 5;
    int x = v;
#pragma unroll
    for (int off = 1; off < 32; off <<= 1) {
        int t = __shfl_up_sync(0xffffffffu, x, off);
        if (lane >= off) x += t;
    }
    if (lane == 31) wsum[w] = x;
    __syncthreads();
    if (w == 0) {
        int s = (lane < 16) ? wsum[lane] : 0;
#pragma unroll
        for (int off = 1; off < 16; off <<= 1) {
            int t = __shfl_up_sync(0xffffffffu, s, off);
            if (lane >= off) s += t;
        }
        if (lane < 16) wsum[lane] = s;
    }
    __syncthreads();
    int base = (w > 0) ? wsum[w - 1] : 0;
    int incl = base + x;
    if (i < NN) g_rowptr[i] = incl - v;
    if (tid == SCAN_B - 1) g_bsum[b] = incl;
}

__global__ void scan3_kernel() {
    __shared__ int boffs;
    int b = blockIdx.x, tid = threadIdx.x;
    if (tid < 32) {
        int s = 0;
        for (int i = tid; i < b; i += 32) s += g_bsum[i];
#pragma unroll
        for (int off = 16; off >= 1; off >>= 1) s += __shfl_xor_sync(0xffffffffu, s, off);
        if (tid == 0) boffs = s;
    }
    __syncthreads();
    int i = b * SCAN_B + tid;
    if (i < NN) {
        int rp = g_rowptr[i] + boffs;
        g_rowptr[i] = rp;
        g_cursor[i] = rp;
        if (g_deg[i] == 0) {
            int p = atomicAdd(&g_zcount, 1);
            g_zlist[p] = i;
        }
    }
    if (b == 0 && tid == 0) g_rowptr[NN] = EE;
}

__global__ void scatter_kernel() {
    int idx = blockIdx.x * blockDim.x + threadIdx.x;
    int stride = gridDim.x * blockDim.x;
    for (int i = idx; i < EE; i += stride) {
        int d = g_dst[i];
        int pos = atomicAdd(&g_cursor[d], 1);
        g_csrc[pos] = g_src[i];
    }
}

// ---------------- encoder + uv fused ----------------
__global__ void encuv_kernel(const float* __restrict__ x, const float* __restrict__ Wenc,
                             const float* __restrict__ benc,
                             const float* __restrict__ Wmsg, const float* __restrict__ bmsg,
                             const float* __restrict__ Wupd, const float* __restrict__ bupd) {
    if (blockIdx.x >= 1184) {
        int k = blockIdx.x - 1184;   // 0..127
        int j = threadIdx.x;         // 0..127
        float u = Wupd[k * HD + j];
        float v = 0.f;
        for (int t = 0; t < HD; t++) {
            float wub = Wupd[(HD + t) * HD + j];
            u += Wmsg[(HD + k) * HD + t] * wub;
            v += Wmsg[k * HD + t] * wub;
        }
        g_U[k * HD + j] = u;
        g_V[k * HD + j] = v;
        if (k == 0) {
            float c = bupd[j];
            for (int t = 0; t < HD; t++) c += bmsg[t] * Wupd[(HD + t) * HD + j];
            g_c1[j] = c;
        }
        return;
    }
    __shared__ float ws[FIN * HD];
    __shared__ float bs[HD];
    __shared__ float xs[FIN];
    int tid = threadIdx.x;  // 128
    for (int i = tid; i < FIN * HD; i += 128) ws[i] = Wenc[i];
    bs[tid] = benc[tid];
    __syncthreads();
    for (int v = blockIdx.x; v < NN; v += 1184) {
        if (tid < FIN) xs[tid] = x[v * FIN + tid];
        __syncthreads();
        float acc = bs[tid];
#pragma unroll
        for (int k = 0; k < FIN; k++) acc += xs[k] * ws[k * HD + tid];
        g_h[v * HD + tid] = acc;
        __syncthreads();
    }
}

// ---------------- fused layer: agg + h' = relu(h@U + A@V + c1) + zero-deg fixup ----------
// 391 GEMM blocks x 2 balanced tiles (single wave at occ 3) + 16 fixup blocks.
#define LAYER_SMEM_FLOATS (8448 + 8448 + 1024)
__global__ void __launch_bounds__(256, 3)
layer_kernel(const float* __restrict__ hcur, float* __restrict__ hnext,
             const int* __restrict__ lnum, int layer,
             const float* __restrict__ Wupd, const float* __restrict__ bupd) {
    if (layer >= *lnum) return;
    int tid = threadIdx.x;
    if (blockIdx.x >= LGRID) {
        __shared__ float hs[HD];
        int zc = g_zcount;
        for (int zi = blockIdx.x - LGRID; zi < zc; zi += 16) {
            int v = g_zlist[zi];
            if (tid < 128) hs[tid] = hcur[v * HD + tid];
            __syncthreads();
            if (tid < 128) {
                float acc = bupd[tid];
#pragma unroll 8
                for (int k = 0; k < HD; k++) acc += hs[k] * Wupd[k * HD + tid];
                hnext[v * HD + tid] = fmaxf(acc, 0.f);
            }
            __syncthreads();
        }
        return;
    }
    extern __shared__ float lsm[];
    float* Hst = lsm;            // [k 128][r 64] stride 66
    float* Ast = Hst + 8448;     // [k 128][r 64] stride 66
    float* Ws  = Ast + 8448;     // [8][128] chunk
    int warp = tid >> 5, lane = tid & 31;

    for (int tile = blockIdx.x; tile < G64; tile += LGRID) {
        int row0 = tile * 64;
        __syncthreads();

        // stage Hst transposed (coalesced reads)
#pragma unroll 4
        for (int q = 0; q < 32; q++) {
            int e = tid + 256 * q;
            int r = e >> 7, k = e & 127;
            int gr = row0 + r;
            Hst[k * 66 + r] = (gr < NN) ? hcur[gr * HD + k] : 0.f;
        }

        // mean-aggregate into Ast (transposed); warp per node, MLP-4 gather
        for (int n = warp; n < 64; n += 8) {
            int v = row0 + n;
            float4 a0 = make_float4(0.f, 0.f, 0.f, 0.f);
            float4 a1 = make_float4(0.f, 0.f, 0.f, 0.f);
            float4 a2 = make_float4(0.f, 0.f, 0.f, 0.f);
            float4 a3 = make_float4(0.f, 0.f, 0.f, 0.f);
            int dg = 0;
            if (v < NN) {
                int s0r = g_rowptr[v], s1r = g_rowptr[v + 1];
                dg = s1r - s0r;
                int idx = s0r;
                for (; idx + 3 < s1r; idx += 4) {
                    int i0 = g_csrc[idx], i1 = g_csrc[idx + 1];
                    int i2 = g_csrc[idx + 2], i3 = g_csrc[idx + 3];
                    float4 h0 = __ldg((const float4*)(hcur + i0 * HD + lane * 4));
                    float4 h1 = __ldg((const float4*)(hcur + i1 * HD + lane * 4));
                    float4 h2 = __ldg((const float4*)(hcur + i2 * HD + lane * 4));
                    float4 h3 = __ldg((const float4*)(hcur + i3 * HD + lane * 4));
                    a0.x += h0.x; a0.y += h0.y; a0.z += h0.z; a0.w += h0.w;
                    a1.x += h1.x; a1.y += h1.y; a1.z += h1.z; a1.w += h1.w;
                    a2.x += h2.x; a2.y += h2.y; a2.z += h2.z; a2.w += h2.w;
                    a3.x += h3.x; a3.y += h3.y; a3.z += h3.z; a3.w += h3.w;
                }
                for (; idx < s1r; idx++) {
                    int i0 = g_csrc[idx];
                    float4 h0 = __ldg((const float4*)(hcur + i0 * HD + lane * 4));
                    a0.x += h0.x; a0.y += h0.y; a0.z += h0.z; a0.w += h0.w;
                }
            }
            float inv = 1.f / (float)(dg > 0 ? dg : 1);
            int j0 = lane * 4;
            Ast[(j0 + 0) * 66 + n] = (a0.x + a1.x + a2.x + a3.x) * inv;
            Ast[(j0 + 1) * 66 + n] = (a0.y + a1.y + a2.y + a3.y) * inv;
            Ast[(j0 + 2) * 66 + n] = (a0.z + a1.z + a2.z + a3.z) * inv;
            Ast[(j0 + 3) * 66 + n] = (a0.w + a1.w + a2.w + a3.w) * inv;
        }
        __syncthreads();

        int jb = warp * 16;
        ull acc[2][8];
        {
            const ulonglong2* cp = (const ulonglong2*)(g_c1 + jb);
            ulonglong2 q0 = cp[0], q1 = cp[1], q2 = cp[2], q3 = cp[3];
            acc[0][0] = q0.x; acc[0][1] = q0.y; acc[0][2] = q1.x; acc[0][3] = q1.y;
            acc[0][4] = q2.x; acc[0][5] = q2.y; acc[0][6] = q3.x; acc[0][7] = q3.y;
#pragma unroll
            for (int i = 0; i < 8; i++) acc[1][i] = acc[0][i];
        }
        for (int pass = 0; pass < 2; pass++) {
            const float* Wg = pass ? g_V : g_U;
            const float* Xt = pass ? Ast : Hst;
            for (int c = 0; c < 16; c++) {
#pragma unroll
                for (int q = 0; q < 4; q++) Ws[tid + 256 * q] = Wg[c * 1024 + tid + 256 * q];
                __syncthreads();
#pragma unroll
                for (int kk = 0; kk < 8; kk++) {
                    const float* wr = Ws + kk * 128 + jb;
                    ulonglong2 wA = *(const ulonglong2*)(wr);
                    ulonglong2 wB = *(const ulonglong2*)(wr + 4);
                    ulonglong2 wC = *(const ulonglong2*)(wr + 8);
                    ulonglong2 wD = *(const ulonglong2*)(wr + 12);
                    float2 xv = *(const float2*)(Xt + (c * 8 + kk) * 66 + lane * 2);
                    ull x0 = pk2(xv.x, xv.x), x1 = pk2(xv.y, xv.y);
                    ffma2(acc[0][0], x0, wA.x); ffma2(acc[0][1], x0, wA.y);
                    ffma2(acc[0][2], x0, wB.x); ffma2(acc[0][3], x0, wB.y);
                    ffma2(acc[0][4], x0, wC.x); ffma2(acc[0][5], x0, wC.y);
                    ffma2(acc[0][6], x0, wD.x); ffma2(acc[0][7], x0, wD.y);
                    ffma2(acc[1][0], x1, wA.x); ffma2(acc[1][1], x1, wA.y);
                    ffma2(acc[1][2], x1, wB.x); ffma2(acc[1][3], x1, wB.y);
                    ffma2(acc[1][4], x1, wC.x); ffma2(acc[1][5], x1, wC.y);
                    ffma2(acc[1][6], x1, wD.x); ffma2(acc[1][7], x1, wD.y);
                }
                __syncthreads();
            }
        }
#pragma unroll
        for (int rr = 0; rr < 2; rr++) {
            int r = row0 + lane * 2 + rr;
            if (r < NN && g_deg[r] != 0) {
                float f[16];
#pragma unroll
                for (int i = 0; i < 8; i++) upk2(acc[rr][i], f[2 * i], f[2 * i + 1]);
                float4* dst = (float4*)(hnext + r * HD + jb);
#pragma unroll
                for (int qq = 0; qq < 4; qq++) {
                    float4 o;
                    o.x = fmaxf(f[4 * qq + 0], 0.f); o.y = fmaxf(f[4 * qq + 1], 0.f);
                    o.z = fmaxf(f[4 * qq + 2], 0.f); o.w = fmaxf(f[4 * qq + 3], 0.f);
                    dst[qq] = o;
                }
            }
        }
    }
}

// ---------------- P/Q: P = h@We1[0:128], Q = h@We1[128:256] ----------------
#define PQ_SMEM_FLOATS (8448 + 2048)
__global__ void pq_kernel(const float* __restrict__ We1, const int* __restrict__ lnum) {
    const float* X = ((*lnum) & 1) ? g_h2 : g_h;
    extern __shared__ float psm[];
    float* Hst  = psm;            // [k 128][r 64] stride 66
    float* Wbuf = Hst + 8448;     // 2048 chunk
    int tid = threadIdx.x;
    int warp = tid >> 5, lane = tid & 31;
    int row0 = blockIdx.x * 64;
#pragma unroll 4
    for (int q = 0; q < 32; q++) {
        int e = tid + 256 * q;
        int r = e >> 7, k = e & 127;
        int gr = row0 + r;
        Hst[k * 66 + r] = (gr < NN) ? X[gr * HD + k] : 0.f;
    }
    __syncthreads();

    int jb = warp * 16;
    for (int m = 0; m < 2; m++) {
        const float* Wg = We1 + m * 128 * HD;
        float* C = m ? g_Q : g_P;
        ull acc[2][8];
        ull z = pk2(0.f, 0.f);
#pragma unroll
        for (int i = 0; i < 8; i++) { acc[0][i] = z; acc[1][i] = z; }
        for (int c = 0; c < 8; c++) {
#pragma unroll
            for (int q = 0; q < 8; q++) Wbuf[tid + 256 * q] = Wg[c * 2048 + tid + 256 * q];
            __syncthreads();
#pragma unroll
            for (int kk = 0; kk < 16; kk++) {
                const float* wr = Wbuf + kk * 128 + jb;
                ulonglong2 wA = *(const ulonglong2*)(wr);
                ulonglong2 wB = *(const ulonglong2*)(wr + 4);
                ulonglong2 wC = *(const ulonglong2*)(wr + 8);
                ulonglong2 wD = *(const ulonglong2*)(wr + 12);
                float2 xv = *(const float2*)(Hst + (c * 16 + kk) * 66 + lane * 2);
                ull x0 = pk2(xv.x, xv.x), x1 = pk2(xv.y, xv.y);
                ffma2(acc[0][0], x0, wA.x); ffma2(acc[0][1], x0, wA.y);
                ffma2(acc[0][2], x0, wB.x); ffma2(acc[0][3], x0, wB.y);
                ffma2(acc[0][4], x0, wC.x); ffma2(acc[0][5], x0, wC.y);
                ffma2(acc[0][6], x0, wD.x); ffma2(acc[0][7], x0, wD.y);
                ffma2(acc[1][0], x1, wA.x); ffma2(acc[1][1], x1, wA.y);
                ffma2(acc[1][2], x1, wB.x); ffma2(acc[1][3], x1, wB.y);
                ffma2(acc[1][4], x1, wC.x); ffma2(acc[1][5], x1, wC.y);
                ffma2(acc[1][6], x1, wD.x); ffma2(acc[1][7], x1, wD.y);
            }
            __syncthreads();
        }
#pragma unroll
        for (int rr = 0; rr < 2; rr++) {
            int r = row0 + lane * 2 + rr;
            if (r < NN) {
                float f[16];
#pragma unroll
                for (int i = 0; i < 8; i++) upk2(acc[rr][i], f[2 * i], f[2 * i + 1]);
                float4* dst = (float4*)(C + r * HD + jb);
#pragma unroll
                for (int qq = 0; qq < 4; qq++) {
                    float4 o;
                    o.x = f[4 * qq + 0]; o.y = f[4 * qq + 1];
                    o.z = f[4 * qq + 2]; o.w = f[4 * qq + 3];
                    dst[qq] = o;
                }
            }
        }
    }
}

// ---------------- node head (runs concurrently with pq/edge on forked stream) --------
#define NH_SMEM_FLOATS (8448 + 2048 + 4352 + 128)
__global__ void nh_kernel(const float* __restrict__ Wn1, const float* __restrict__ bn1,
                          const float* __restrict__ Wn2, const float* __restrict__ bn2,
                          float* __restrict__ out, const int* __restrict__ lnum) {
    const float* X = ((*lnum) & 1) ? g_h2 : g_h;
    extern __shared__ float nsm[];
    float* Hst  = nsm;            // [k 128][r 64] stride 66
    float* Wbuf = Hst + 8448;     // 2048 chunk
    float* tsb  = Wbuf + 2048;    // [r 64][j 64] stride 68
    float* W2s  = tsb + 4352;     // 64*2
    int tid = threadIdx.x;
    int warp = tid >> 5, lane = tid & 31;
    int row0 = blockIdx.x * 64;
    if (tid < 128) W2s[tid] = Wn2[tid];
#pragma unroll 4
    for (int q = 0; q < 32; q++) {
        int e = tid + 256 * q;
        int r = e >> 7, k = e & 127;
        int gr = row0 + r;
        Hst[k * 66 + r] = (gr < NN) ? X[gr * HD + k] : 0.f;
    }
    __syncthreads();

    int jb8 = warp * 8;
    ull acc2[2][4];
    {
        ulonglong2 b01 = *(const ulonglong2*)(bn1 + jb8);
        ulonglong2 b23 = *(const ulonglong2*)(bn1 + jb8 + 4);
        acc2[0][0] = b01.x; acc2[0][1] = b01.y; acc2[0][2] = b23.x; acc2[0][3] = b23.y;
#pragma unroll
        for (int i = 0; i < 4; i++) acc2[1][i] = acc2[0][i];
    }
    for (int c = 0; c < 4; c++) {
#pragma unroll
        for (int q = 0; q < 8; q++) Wbuf[tid + 256 * q] = Wn1[c * 2048 + tid + 256 * q];
        __syncthreads();
#pragma unroll 8
        for (int kk = 0; kk < 32; kk++) {
            const float* wr = Wbuf + kk * 64 + jb8;
            ulonglong2 wA = *(const ulonglong2*)(wr);
            ulonglong2 wB = *(const ulonglong2*)(wr + 4);
            float2 xv = *(const float2*)(Hst + (c * 32 + kk) * 66 + lane * 2);
            ull x0 = pk2(xv.x, xv.x), x1 = pk2(xv.y, xv.y);
            ffma2(acc2[0][0], x0, wA.x); ffma2(acc2[0][1], x0, wA.y);
            ffma2(acc2[0][2], x0, wB.x); ffma2(acc2[0][3], x0, wB.y);
            ffma2(acc2[1][0], x1, wA.x); ffma2(acc2[1][1], x1, wA.y);
            ffma2(acc2[1][2], x1, wB.x); ffma2(acc2[1][3], x1, wB.y);
        }
        __syncthreads();
    }
#pragma unroll
    for (int rr = 0; rr < 2; rr++) {
        int r = lane * 2 + rr;
        float f[8];
#pragma unroll
        for (int i = 0; i < 4; i++) upk2(acc2[rr][i], f[2 * i], f[2 * i + 1]);
        float4 o1, o2;
        o1.x = fmaxf(f[0], 0.f); o1.y = fmaxf(f[1], 0.f); o1.z = fmaxf(f[2], 0.f); o1.w = fmaxf(f[3], 0.f);
        o2.x = fmaxf(f[4], 0.f); o2.y = fmaxf(f[5], 0.f); o2.z = fmaxf(f[6], 0.f); o2.w = fmaxf(f[7], 0.f);
        *(float4*)(tsb + r * 68 + jb8) = o1;
        *(float4*)(tsb + r * 68 + jb8 + 4) = o2;
    }
    __syncthreads();
    if (tid < 128) {
        int r = tid >> 1, o = tid & 1;
        float s = 0.f;
#pragma unroll 8
        for (int j = 0; j < 64; j++) s += tsb[r * 68 + j] * W2s[j * 2 + o];
        int gr = row0 + r;
        if (gr < NN) out[gr * 2 + o] = s + bn2[o];
    }
}

// ---------------- fused edge head ----------------
#define EDGE_SMEM_FLOATS (16896 + 8704 + 384 + 8)
#define P2STEP(CMP, JJ)                                                              \
    {                                                                                \
        const ulonglong2* wp = (const ulonglong2*)(wbase + (JJ) * 64);               \
        ulonglong2 wA = __ldg(wp);                                                   \
        ulonglong2 wB = __ldg(wp + 1);                                               \
        ull x0 = pk2(t0.CMP, t0.CMP), x1 = pk2(t1.CMP, t1.CMP);                      \
        ull x2 = pk2(t2.CMP, t2.CMP), x3 = pk2(t3.CMP, t3.CMP);                      \
        ffma2(acc[0][0], x0, wA.x); ffma2(acc[0][1], x0, wA.y);                      \
        ffma2(acc[0][2], x0, wB.x); ffma2(acc[0][3], x0, wB.y);                      \
        ffma2(acc[1][0], x1, wA.x); ffma2(acc[1][1], x1, wA.y);                      \
        ffma2(acc[1][2], x1, wB.x); ffma2(acc[1][3], x1, wB.y);                      \
        ffma2(acc[2][0], x2, wA.x); ffma2(acc[2][1], x2, wA.y);                      \
        ffma2(acc[2][2], x2, wB.x); ffma2(acc[2][3], x2, wB.y);                      \
        ffma2(acc[3][0], x3, wA.x); ffma2(acc[3][1], x3, wA.y);                      \
        ffma2(acc[3][2], x3, wB.x); ffma2(acc[3][3], x3, wB.y);                      \
    }
__global__ void __launch_bounds__(256, 2)
edge_kernel(const float* __restrict__ ea, const float* __restrict__ We1,
            const float* __restrict__ be1, const float* __restrict__ We2,
            const float* __restrict__ be2, const float* __restrict__ We3,
            const float* __restrict__ be3, float* __restrict__ out) {
    extern __shared__ float esm[];
    float* ts  = esm;             // [128 el][132 j]
    float* us  = ts + 16896;      // [128 el][68 j]
    float* w3t = us + 8704;       // [6][64] transposed
    float* b3s = w3t + 384;       // 8
    __shared__ int esrc[128], edst[128];
    int tid = threadIdx.x, warp = tid >> 5, lane = tid & 31;
    int j0 = lane * 4;

    for (int i = tid; i < 384; i += 256) w3t[i] = We3[(i & 63) * 6 + (i >> 6)];
    if (tid < 8) b3s[tid] = (tid < 6) ? be3[tid] : 0.f;

    float4 bq = __ldg((const float4*)(be1 + j0));
    float4 wck[8];
#pragma unroll
    for (int k = 0; k < 8; k++)
        wck[k] = __ldg((const float4*)(We1 + 256 * HD + k * 128 + j0));
    int jb = warp * 8;
    ulonglong2 b2a = __ldg((const ulonglong2*)(be2 + jb));
    ulonglong2 b2b = __ldg((const ulonglong2*)(be2 + jb + 4));
    __syncthreads();

    for (int e0 = blockIdx.x * 128; e0 < EE; e0 += gridDim.x * 128) {
        if (tid < 128) {
            int e = e0 + tid;
            esrc[tid] = g_src[e];
            edst[tid] = g_dst[e];
        }
        __syncthreads();
        // ---- phase 1 ----
        for (int it = 0; it < 8; it++) {
            int elA = warp + 8 * (2 * it);
            int elB = elA + 8;
            int sA = esrc[elA], dA = edst[elA];
            int sB = esrc[elB], dB = edst[elB];
            float4 pA = __ldg((const float4*)(g_P + sA * HD + j0));
            float4 qA = __ldg((const float4*)(g_Q + dA * HD + j0));
            float4 pB = __ldg((const float4*)(g_P + sB * HD + j0));
            float4 qB = __ldg((const float4*)(g_Q + dB * HD + j0));
            float4 eA0 = __ldg((const float4*)(ea + (e0 + elA) * EAD));
            float4 eA1 = __ldg((const float4*)(ea + (e0 + elA) * EAD + 4));
            float4 eB0 = __ldg((const float4*)(ea + (e0 + elB) * EAD));
            float4 eB1 = __ldg((const float4*)(ea + (e0 + elB) * EAD + 4));
            float4 t = bq;
            t.x += eA0.x * wck[0].x + eA0.y * wck[1].x + eA0.z * wck[2].x + eA0.w * wck[3].x
                 + eA1.x * wck[4].x + eA1.y * wck[5].x + eA1.z * wck[6].x + eA1.w * wck[7].x;
            t.y += eA0.x * wck[0].y + eA0.y * wck[1].y + eA0.z * wck[2].y + eA0.w * wck[3].y
                 + eA1.x * wck[4].y + eA1.y * wck[5].y + eA1.z * wck[6].y + eA1.w * wck[7].y;
            t.z += eA0.x * wck[0].z + eA0.y * wck[1].z + eA0.z * wck[2].z + eA0.w * wck[3].z
                 + eA1.x * wck[4].z + eA1.y * wck[5].z + eA1.z * wck[6].z + eA1.w * wck[7].z;
            t.w += eA0.x * wck[0].w + eA0.y * wck[1].w + eA0.z * wck[2].w + eA0.w * wck[3].w
                 + eA1.x * wck[4].w + eA1.y * wck[5].w + eA1.z * wck[6].w + eA1.w * wck[7].w;
            t.x = fmaxf(t.x + pA.x + qA.x, 0.f);
            t.y = fmaxf(t.y + pA.y + qA.y, 0.f);
            t.z = fmaxf(t.z + pA.z + qA.z, 0.f);
            t.w = fmaxf(t.w + pA.w + qA.w, 0.f);
            *(float4*)(ts + elA * 132 + j0) = t;
            float4 u = bq;
            u.x += eB0.x * wck[0].x + eB0.y * wck[1].x + eB0.z * wck[2].x + eB0.w * wck[3].x
                 + eB1.x * wck[4].x + eB1.y * wck[5].x + eB1.z * wck[6].x + eB1.w * wck[7].x;
            u.y += eB0.x * wck[0].y + eB0.y * wck[1].y + eB0.z * wck[2].y + eB0.w * wck[3].y
                 + eB1.x * wck[4].y + eB1.y * wck[5].y + eB1.z * wck[6].y + eB1.w * wck[7].y;
            u.z += eB0.x * wck[0].z + eB0.y * wck[1].z + eB0.z * wck[2].z + eB0.w * wck[3].z
                 + eB1.x * wck[4].z + eB1.y * wck[5].z + eB1.z * wck[6].z + eB1.w * wck[7].z;
            u.w += eB0.x * wck[0].w + eB0.y * wck[1].w + eB0.z * wck[2].w + eB0.w * wck[3].w
                 + eB1.x * wck[4].w + eB1.y * wck[5].w + eB1.z * wck[6].w + eB1.w * wck[7].w;
            u.x = fmaxf(u.x + pB.x + qB.x, 0.f);
            u.y = fmaxf(u.y + pB.y + qB.y, 0.f);
            u.z = fmaxf(u.z + pB.z + qB.z, 0.f);
            u.w = fmaxf(u.w + pB.w + qB.w, 0.f);
            *(float4*)(ts + elB * 132 + j0) = u;
        }
        __syncthreads();
        // ---- phase 2 ----
        ull acc[4][4];
#pragma unroll
        for (int e = 0; e < 4; e++) {
            acc[e][0] = b2a.x; acc[e][1] = b2a.y; acc[e][2] = b2b.x; acc[e][3] = b2b.y;
        }
#pragma unroll 2
        for (int jv = 0; jv < 128; jv += 4) {
            float4 t0 = *(const float4*)(ts + (lane) * 132 + jv);
            float4 t1 = *(const float4*)(ts + (lane + 32) * 132 + jv);
            float4 t2 = *(const float4*)(ts + (lane + 64) * 132 + jv);
            float4 t3 = *(const float4*)(ts + (lane + 96) * 132 + jv);
            const float* wbase = We2 + jv * 64 + jb;
            P2STEP(x, 0)
            P2STEP(y, 1)
            P2STEP(z, 2)
            P2STEP(w, 3)
        }
#pragma unroll
        for (int e = 0; e < 4; e++) {
            int el = lane + 32 * e;
            float f[8];
#pragma unroll
            for (int i = 0; i < 4; i++) upk2(acc[e][i], f[2 * i], f[2 * i + 1]);
            float4 o1, o2;
            o1.x = fmaxf(f[0], 0.f); o1.y = fmaxf(f[1], 0.f); o1.z = fmaxf(f[2], 0.f); o1.w = fmaxf(f[3], 0.f);
            o2.x = fmaxf(f[4], 0.f); o2.y = fmaxf(f[5], 0.f); o2.z = fmaxf(f[6], 0.f); o2.w = fmaxf(f[7], 0.f);
            *(float4*)(us + el * 68 + jb) = o1;
            *(float4*)(us + el * 68 + jb + 4) = o2;
        }
        __syncthreads();
        // ---- phase 3 ----
        {
            int el = tid >> 1;
            int o3 = (tid & 1) * 3;
            float a0 = b3s[o3], a1 = b3s[o3 + 1], a2 = b3s[o3 + 2];
#pragma unroll
            for (int q = 0; q < 16; q++) {
                float4 u = *(const float4*)(us + el * 68 + 4 * q);
                float4 w0 = *(const float4*)(w3t + (o3 + 0) * 64 + 4 * q);
                float4 w1 = *(const float4*)(w3t + (o3 + 1) * 64 + 4 * q);
                float4 w2 = *(const float4*)(w3t + (o3 + 2) * 64 + 4 * q);
                a0 += u.x * w0.x + u.y * w0.y + u.z * w0.z + u.w * w0.w;
                a1 += u.x * w1.x + u.y * w1.y + u.z * w1.z + u.w * w1.w;
                a2 += u.x * w2.x + u.y * w2.y + u.z * w2.z + u.w * w2.w;
            }
            int e = e0 + el;
            out[e * 6 + o3 + 0] = a0;
            out[e * 6 + o3 + 1] = a1;
            out[e * 6 + o3 + 2] = a2;
        }
        __syncthreads();
    }
}

// ---------------- launch ----------------
extern "C" void kernel_launch(void* const* d_in, const int* in_sizes, int n_in,
                              void* d_out, int out_size) {
    const float* x    = (const float*)d_in[0];
    const void*  ei   = d_in[1];
    const float* ea   = (const float*)d_in[2];
    const int*   lnum = (const int*)d_in[3];
    const float* Wenc = (const float*)d_in[4];
    const float* benc = (const float*)d_in[5];
    const float* Wmsg = (const float*)d_in[6];
    const float* bmsg = (const float*)d_in[7];
    const float* Wupd = (const float*)d_in[8];
    const float* bupd = (const float*)d_in[9];
    const float* Wn1  = (const float*)d_in[10];
    const float* bn1  = (const float*)d_in[11];
    const float* Wn2  = (const float*)d_in[12];
    const float* bn2  = (const float*)d_in[13];
    const float* We1  = (const float*)d_in[14];
    const float* be1  = (const float*)d_in[15];
    const float* We2  = (const float*)d_in[16];
    const float* be2  = (const float*)d_in[17];
    const float* We3  = (const float*)d_in[18];
    const float* be3  = (const float*)d_in[19];
    float* out = (float*)d_out;

    float *hp, *h2p;
    cudaGetSymbolAddress((void**)&hp,  g_h);
    cudaGetSymbolAddress((void**)&h2p, g_h2);

    const int layerSmem = LAYER_SMEM_FLOATS * 4;
    const int pqSmem    = PQ_SMEM_FLOATS * 4;
    const int nhSmem    = NH_SMEM_FLOATS * 4;
    const int edgeSmem  = EDGE_SMEM_FLOATS * 4;
    cudaFuncSetAttribute(layer_kernel, cudaFuncAttributeMaxDynamicSharedMemorySize, layerSmem);
    cudaFuncSetAttribute(pq_kernel, cudaFuncAttributeMaxDynamicSharedMemorySize, pqSmem);
    cudaFuncSetAttribute(nh_kernel, cudaFuncAttributeMaxDynamicSharedMemorySize, nhSmem);
    cudaFuncSetAttribute(edge_kernel, cudaFuncAttributeMaxDynamicSharedMemorySize, edgeSmem);

    cudaStream_t s0 = 0;
    bool fork = s_fork;

    detect_kernel<<<256, 256, 0, s0>>>((const long long*)ei);
    if (fork) {
        cudaEventRecord(s_ev0, s0);
        cudaStreamWaitEvent(s_b, s_ev0, 0);
        encuv_kernel<<<1312, 128, 0, s_b>>>(x, Wenc, benc, Wmsg, bmsg, Wupd, bupd);
        cudaEventRecord(s_evB, s_b);
    }
    prep_kernel<<<1024, 256, 0, s0>>>(ei);
    scan1_kernel<<<SCAN_NB, SCAN_B, 0, s0>>>();
    scan3_kernel<<<SCAN_NB, SCAN_B, 0, s0>>>();
    scatter_kernel<<<1024, 256, 0, s0>>>();
    if (fork) {
        cudaStreamWaitEvent(s0, s_evB, 0);
    } else {
        encuv_kernel<<<1312, 128, 0, s0>>>(x, Wenc, benc, Wmsg, bmsg, Wupd, bupd);
    }

    for (int L = 0; L < MAX_LAYERS; L++) {
        const float* cur = (L & 1) ? h2p : hp;
        float* nxt = (L & 1) ? hp : h2p;
        layer_kernel<<<LGRID + 16, 256, layerSmem, s0>>>(cur, nxt, lnum, L, Wupd, bupd);
    }

    if (fork) {
        cudaEventRecord(s_ev1, s0);
        cudaStreamWaitEvent(s_b, s_ev1, 0);
        nh_kernel<<<G64, 256, nhSmem, s_b>>>(Wn1, bn1, Wn2, bn2, out, lnum);
        cudaEventRecord(s_evB2, s_b);
    } else {
        nh_kernel<<<G64, 256, nhSmem, s0>>>(Wn1, bn1, Wn2, bn2, out, lnum);
    }
    pq_kernel<<<G64, 256, pqSmem, s0>>>(We1, lnum);
    edge_kernel<<<296, 256, edgeSmem, s0>>>(ea, We1, be1, We2, be2, We3, be3, out + NODE_OUT_ELEMS);
    if (fork) {
        cudaStreamWaitEvent(s0, s_evB2, 0);
    }
}